// round 5
// baseline (speedup 1.0000x reference)
#include <cuda_runtime.h>
#include <math.h>

#define BATCH 8
#define CIN   128
#define DIM   256
#define NSLOT 64
#define LTOK  4096

typedef unsigned long long u64;

__device__ __forceinline__ u64 PK1(float v) {
    u64 r; asm("mov.b64 %0, {%1,%1};" : "=l"(r) : "f"(v)); return r;
}
__device__ __forceinline__ void FMA2(u64& d, u64 a, u64 b) {
    asm("fma.rn.f32x2 %0, %1, %2, %0;" : "+l"(d) : "l"(a), "l"(b));
}
__device__ __forceinline__ float2 UPK(u64 v) {
    float2 f; asm("mov.b64 {%0,%1}, %2;" : "=f"(f.x), "=f"(f.y) : "l"(v)); return f;
}

// ---------------- scratch ----------------
__device__ float g_wt[3456*256];
__device__ float g_k[BATCH*LTOK*DIM];
__device__ float g_v[BATCH*LTOK*DIM];
__device__ float g_templates[BATCH*NSLOT*DIM];
__device__ float g_tbuf[BATCH*NSLOT*DIM];
__device__ float g_q[BATCH*NSLOT*DIM];
__device__ float g_attn[BATCH*LTOK*NSLOT];
__device__ float g_colsum_part[BATCH*64*NSLOT];
__device__ float g_colsum[BATCH*NSLOT];
__device__ float g_accpart[8*BATCH*NSLOT*DIM];
__device__ float g_hidden[BATCH*NSLOT*512];

__device__ __forceinline__ float gelu_exact(float v) {
    return 0.5f * v * (1.0f + erff(v * 0.70710678118654752f));
}

// ---------------- prep ----------------
__global__ void wt_transpose_kernel(const float* __restrict__ cw) {
    g_wt[blockIdx.x * 256 + threadIdx.x] = cw[threadIdx.x * 3456 + blockIdx.x];
}

__global__ void templates_init_kernel(const float* __restrict__ tinit) {
    int b = blockIdx.x, t = threadIdx.x;
    for (int n = 0; n < NSLOT; n++)
        g_templates[(b*NSLOT + n)*DIM + t] = tinit[n*DIM + t];
}

// ---------------- conv3d + ReLU + LN + K/V projection ----------------
#define CONV_SMEM_FLOATS (38016 + 16*256)
__global__ __launch_bounds__(256) void conv_ln_kv_kernel(
    const float* __restrict__ x, const float* __restrict__ convb,
    const float* __restrict__ lng, const float* __restrict__ lnb,
    const float* __restrict__ Wk, const float* __restrict__ Wv)
{
    extern __shared__ float sm[];
    float* patch = sm;            // [c_in*9][33]
    float* toks  = sm + 38016;    // [16][256]

    int bid = blockIdx.x;
    int b  = bid >> 8;
    int xd = (bid >> 4) & 15;
    int xh = bid & 15;
    int t = threadIdx.x;
    int warp = t >> 5, lane = t & 31;

    const float* xb = x + (size_t)b * (CIN*33*33*33);
    for (int r = warp; r < 1152; r += 8) {
        int c = r / 9; int rem = r - c*9; int kd = rem / 3; int kh = rem - kd*3;
        const float* src = xb + ((size_t)(c*33 + (2*xd+kd))*33 + (2*xh+kh))*33;
        patch[r*33 + lane] = src[lane];
        if (lane == 0) patch[r*33 + 32] = src[32];
    }
    __syncthreads();

    int c4 = t & 63;   // 4 c_out (2 f32x2 pairs)
    int tq = t >> 6;   // 4 tokens
    u64 acc[4][2];
    {
        ulonglong2 b2 = *(const ulonglong2*)(convb + c4*4);
        #pragma unroll
        for (int i = 0; i < 4; i++) { acc[i][0] = b2.x; acc[i][1] = b2.y; }
    }

    const ulonglong2* wt = ((const ulonglong2*)g_wt) + c4;  // row stride 64
    const int wb = 8*tq;

    for (int c = 0; c < CIN; c++) {
        const float* prow = patch + c*297;
        const ulonglong2* wrow = wt + (size_t)(c*27)*64;
        #pragma unroll
        for (int kd = 0; kd < 3; kd++) {
            #pragma unroll
            for (int kh = 0; kh < 3; kh++) {
                const float* pr = prow + (kd*3 + kh)*33 + wb;
                const ulonglong2* wr = wrow + (kd*9 + kh*3)*64;
                #pragma unroll
                for (int kw = 0; kw < 3; kw++) {
                    ulonglong2 w = wr[(size_t)kw*64];
                    u64 q0 = PK1(pr[kw]);
                    u64 q1 = PK1(pr[kw+2]);
                    u64 q2 = PK1(pr[kw+4]);
                    u64 q3 = PK1(pr[kw+6]);
                    FMA2(acc[0][0], w.x, q0); FMA2(acc[0][1], w.y, q0);
                    FMA2(acc[1][0], w.x, q1); FMA2(acc[1][1], w.y, q1);
                    FMA2(acc[2][0], w.x, q2); FMA2(acc[2][1], w.y, q2);
                    FMA2(acc[3][0], w.x, q3); FMA2(acc[3][1], w.y, q3);
                }
            }
        }
    }

    #pragma unroll
    for (int i = 0; i < 4; i++) {
        float2 a = UPK(acc[i][0]), bb2 = UPK(acc[i][1]);
        float4 o;
        o.x = fmaxf(a.x, 0.f);  o.y = fmaxf(a.y, 0.f);
        o.z = fmaxf(bb2.x, 0.f); o.w = fmaxf(bb2.y, 0.f);
        *(float4*)(toks + (4*tq+i)*256 + c4*4) = o;
    }
    __syncthreads();

    // LayerNorm per token (16 threads/row)
    {
        int r = t >> 4, part = t & 15;
        float* row = toks + r*256 + part*16;
        float s = 0.f, sq = 0.f;
        #pragma unroll
        for (int i = 0; i < 16; i += 4) {
            float4 v = *(float4*)(row + i);
            s += v.x+v.y+v.z+v.w;
            sq += v.x*v.x + v.y*v.y + v.z*v.z + v.w*v.w;
        }
        #pragma unroll
        for (int m = 1; m < 16; m <<= 1) {
            s  += __shfl_xor_sync(0xffffffffu, s, m);
            sq += __shfl_xor_sync(0xffffffffu, sq, m);
        }
        float mu = s * (1.0f/256.0f);
        float var = sq * (1.0f/256.0f) - mu*mu;
        float rs = rsqrtf(var + 1e-5f);
        #pragma unroll
        for (int i = 0; i < 16; i++) {
            int ch = part*16 + i;
            row[i] = (row[i] - mu) * rs * lng[ch] + lnb[ch];
        }
    }
    __syncthreads();

    // K/V projections (f32x2)
    {
        u64 ka[4][2] = {}, va[4][2] = {};
        const ulonglong2* wk2 = ((const ulonglong2*)Wk) + c4;
        const ulonglong2* wv2 = ((const ulonglong2*)Wv) + c4;
        const float* t0 = toks + (4*tq+0)*256;
        const float* t1 = toks + (4*tq+1)*256;
        const float* t2 = toks + (4*tq+2)*256;
        const float* t3 = toks + (4*tq+3)*256;
        #pragma unroll 4
        for (int j = 0; j < 256; j++) {
            ulonglong2 kw = wk2[(size_t)j*64];
            ulonglong2 vw = wv2[(size_t)j*64];
            u64 p0 = PK1(t0[j]), p1 = PK1(t1[j]), p2 = PK1(t2[j]), p3 = PK1(t3[j]);
            FMA2(ka[0][0],kw.x,p0); FMA2(ka[0][1],kw.y,p0); FMA2(va[0][0],vw.x,p0); FMA2(va[0][1],vw.y,p0);
            FMA2(ka[1][0],kw.x,p1); FMA2(ka[1][1],kw.y,p1); FMA2(va[1][0],vw.x,p1); FMA2(va[1][1],vw.y,p1);
            FMA2(ka[2][0],kw.x,p2); FMA2(ka[2][1],kw.y,p2); FMA2(va[2][0],vw.x,p2); FMA2(va[2][1],vw.y,p2);
            FMA2(ka[3][0],kw.x,p3); FMA2(ka[3][1],kw.y,p3); FMA2(va[3][0],vw.x,p3); FMA2(va[3][1],vw.y,p3);
        }
        int lbase = ((xd*16 + xh)*16) + 4*tq;
        size_t o0 = ((size_t)b*LTOK + lbase)*DIM + c4*4;
        #pragma unroll
        for (int i = 0; i < 4; i++) {
            *(ulonglong2*)(g_k + o0 + (size_t)i*DIM) = make_ulonglong2(ka[i][0], ka[i][1]);
            *(ulonglong2*)(g_v + o0 + (size_t)i*DIM) = make_ulonglong2(va[i][0], va[i][1]);
        }
    }
}

// ---------------- fused LN_t + q-GEMM ----------------
// grid (4, 8), block 256. smem: Af[256*64] transposed LN'd A + Bs[16*64]
__global__ __launch_bounds__(256) void gemm_q_kernel(
    const float* __restrict__ Wq, const float* __restrict__ lng, const float* __restrict__ lnb)
{
    extern __shared__ float sm[];
    float* Af = sm;            // [k][m] 256x64
    float* Bs = sm + 16384;
    int b = blockIdx.y; int nc = blockIdx.x * 64;
    int t = threadIdx.x;

    // LN staging: 4 threads/row, write transposed
    {
        int r = t >> 2, part = t & 3;
        const float* row = g_templates + ((size_t)(b*NSLOT) + r)*DIM + part*64;
        float s = 0.f, sq = 0.f;
        #pragma unroll
        for (int i = 0; i < 64; i += 4) {
            float4 v = *(const float4*)(row + i);
            s += v.x+v.y+v.z+v.w;
            sq += v.x*v.x + v.y*v.y + v.z*v.z + v.w*v.w;
        }
        s  += __shfl_xor_sync(0xffffffffu, s, 1);  s  += __shfl_xor_sync(0xffffffffu, s, 2);
        sq += __shfl_xor_sync(0xffffffffu, sq, 1); sq += __shfl_xor_sync(0xffffffffu, sq, 2);
        float mu = s * (1.0f/256.0f);
        float rs = rsqrtf(sq * (1.0f/256.0f) - mu*mu + 1e-5f);
        #pragma unroll
        for (int i = 0; i < 64; i += 4) {
            float4 v = *(const float4*)(row + i);
            float4 gg = *(const float4*)(lng + part*64 + i);
            float4 bv = *(const float4*)(lnb + part*64 + i);
            Af[(part*64+i+0)*64 + r] = (v.x - mu)*rs*gg.x + bv.x;
            Af[(part*64+i+1)*64 + r] = (v.y - mu)*rs*gg.y + bv.y;
            Af[(part*64+i+2)*64 + r] = (v.z - mu)*rs*gg.z + bv.z;
            Af[(part*64+i+3)*64 + r] = (v.w - mu)*rs*gg.w + bv.w;
        }
    }
    __syncthreads();

    int tm = t >> 4, tn = t & 15;
    u64 acc[4][2] = {};
    int kk0 = t >> 4, n4 = (t & 15)*4;
    for (int k0 = 0; k0 < 256; k0 += 16) {
        *(float4*)(Bs + kk0*64 + n4) = *(const float4*)(Wq + (size_t)(k0+kk0)*256 + nc + n4);
        __syncthreads();
        #pragma unroll
        for (int kk = 0; kk < 16; kk++) {
            ulonglong2 a2 = *(ulonglong2*)(Af + (k0+kk)*64 + tm*4);
            float4 bb = *(float4*)(Bs + kk*64 + tn*4);
            u64 q0 = PK1(bb.x), q1 = PK1(bb.y), q2 = PK1(bb.z), q3 = PK1(bb.w);
            FMA2(acc[0][0], a2.x, q0); FMA2(acc[0][1], a2.y, q0);
            FMA2(acc[1][0], a2.x, q1); FMA2(acc[1][1], a2.y, q1);
            FMA2(acc[2][0], a2.x, q2); FMA2(acc[2][1], a2.y, q2);
            FMA2(acc[3][0], a2.x, q3); FMA2(acc[3][1], a2.y, q3);
        }
        __syncthreads();
    }
    const float scale = 0.0625f;
    #pragma unroll
    for (int p = 0; p < 2; p++) {
        float2 f0 = UPK(acc[0][p]), f1 = UPK(acc[1][p]), f2 = UPK(acc[2][p]), f3 = UPK(acc[3][p]);
        float4 r0 = {f0.x*scale, f1.x*scale, f2.x*scale, f3.x*scale};
        float4 r1 = {f0.y*scale, f1.y*scale, f2.y*scale, f3.y*scale};
        int m = tm*4 + p*2;
        *(float4*)(g_q + ((size_t)(b*NSLOT) + m  )*DIM + nc + tn*4) = r0;
        *(float4*)(g_q + ((size_t)(b*NSLOT) + m+1)*DIM + nc + tn*4) = r1;
    }
}

// ---------------- hidden = GELU(LN_m(templates) @ W1 + b1), A = g_tbuf ----------------
__global__ __launch_bounds__(256) void gemm_h_kernel(const float* __restrict__ W1,
                                                     const float* __restrict__ b1)
{
    extern __shared__ float sm[];
    float* Af = sm; float* Bs = sm + 16384;
    int b = blockIdx.y; int nc = blockIdx.x * 64;
    int t = threadIdx.x;
    {
        int r = t >> 2, part = t & 3;
        const float* row = g_tbuf + ((size_t)(b*NSLOT) + r)*DIM + part*64;
        #pragma unroll
        for (int i = 0; i < 64; i += 4) {
            float4 v = *(const float4*)(row + i);
            Af[(part*64+i+0)*64 + r] = v.x;
            Af[(part*64+i+1)*64 + r] = v.y;
            Af[(part*64+i+2)*64 + r] = v.z;
            Af[(part*64+i+3)*64 + r] = v.w;
        }
    }
    __syncthreads();
    int tm = t >> 4, tn = t & 15;
    u64 acc[4][2] = {};
    int kk0 = t >> 4, n4 = (t & 15)*4;
    for (int k0 = 0; k0 < 256; k0 += 16) {
        *(float4*)(Bs + kk0*64 + n4) = *(const float4*)(W1 + (size_t)(k0+kk0)*512 + nc + n4);
        __syncthreads();
        #pragma unroll
        for (int kk = 0; kk < 16; kk++) {
            ulonglong2 a2 = *(ulonglong2*)(Af + (k0+kk)*64 + tm*4);
            float4 bb = *(float4*)(Bs + kk*64 + tn*4);
            u64 q0 = PK1(bb.x), q1 = PK1(bb.y), q2 = PK1(bb.z), q3 = PK1(bb.w);
            FMA2(acc[0][0], a2.x, q0); FMA2(acc[0][1], a2.y, q0);
            FMA2(acc[1][0], a2.x, q1); FMA2(acc[1][1], a2.y, q1);
            FMA2(acc[2][0], a2.x, q2); FMA2(acc[2][1], a2.y, q2);
            FMA2(acc[3][0], a2.x, q3); FMA2(acc[3][1], a2.y, q3);
        }
        __syncthreads();
    }
    float4 bv = *(const float4*)(b1 + nc + tn*4);
    #pragma unroll
    for (int p = 0; p < 2; p++) {
        float2 f0 = UPK(acc[0][p]), f1 = UPK(acc[1][p]), f2 = UPK(acc[2][p]), f3 = UPK(acc[3][p]);
        float4 r0 = {gelu_exact(f0.x+bv.x), gelu_exact(f1.x+bv.y), gelu_exact(f2.x+bv.z), gelu_exact(f3.x+bv.w)};
        float4 r1 = {gelu_exact(f0.y+bv.x), gelu_exact(f1.y+bv.y), gelu_exact(f2.y+bv.z), gelu_exact(f3.y+bv.w)};
        int m = tm*4 + p*2;
        *(float4*)(g_hidden + ((size_t)(b*NSLOT) + m  )*512 + nc + tn*4) = r0;
        *(float4*)(g_hidden + ((size_t)(b*NSLOT) + m+1)*512 + nc + tn*4) = r1;
    }
}

// ---------------- templates += hidden @ W2 + b2 ----------------
#define GEMMO_SMEM_FLOATS (32768 + 1024)
__global__ __launch_bounds__(256) void gemm_o_kernel(const float* __restrict__ W2,
                                                     const float* __restrict__ b2)
{
    extern __shared__ float sm[];
    float* Af = sm;            // 512 x 64
    float* Bs = sm + 32768;
    int b = blockIdx.y; int nc = blockIdx.x * 64;
    int t = threadIdx.x;
    {
        int r = t >> 2, part = t & 3;
        const float* row = g_hidden + ((size_t)(b*NSLOT) + r)*512 + part*128;
        #pragma unroll
        for (int i = 0; i < 128; i += 4) {
            float4 v = *(const float4*)(row + i);
            Af[(part*128+i+0)*64 + r] = v.x;
            Af[(part*128+i+1)*64 + r] = v.y;
            Af[(part*128+i+2)*64 + r] = v.z;
            Af[(part*128+i+3)*64 + r] = v.w;
        }
    }
    __syncthreads();
    int tm = t >> 4, tn = t & 15;
    u64 acc[4][2] = {};
    int kk0 = t >> 4, n4 = (t & 15)*4;
    for (int k0 = 0; k0 < 512; k0 += 16) {
        *(float4*)(Bs + kk0*64 + n4) = *(const float4*)(W2 + (size_t)(k0+kk0)*256 + nc + n4);
        __syncthreads();
        #pragma unroll
        for (int kk = 0; kk < 16; kk++) {
            ulonglong2 a2 = *(ulonglong2*)(Af + (k0+kk)*64 + tm*4);
            float4 bb = *(float4*)(Bs + kk*64 + tn*4);
            u64 q0 = PK1(bb.x), q1 = PK1(bb.y), q2 = PK1(bb.z), q3 = PK1(bb.w);
            FMA2(acc[0][0], a2.x, q0); FMA2(acc[0][1], a2.y, q0);
            FMA2(acc[1][0], a2.x, q1); FMA2(acc[1][1], a2.y, q1);
            FMA2(acc[2][0], a2.x, q2); FMA2(acc[2][1], a2.y, q2);
            FMA2(acc[3][0], a2.x, q3); FMA2(acc[3][1], a2.y, q3);
        }
        __syncthreads();
    }
    float4 bv = *(const float4*)(b2 + nc + tn*4);
    #pragma unroll
    for (int p = 0; p < 2; p++) {
        float2 f0 = UPK(acc[0][p]), f1 = UPK(acc[1][p]), f2 = UPK(acc[2][p]), f3 = UPK(acc[3][p]);
        int m = tm*4 + p*2;
        float* C0 = g_templates + ((size_t)(b*NSLOT) + m)*DIM + nc + tn*4;
        float4 c0 = *(float4*)C0;
        c0.x += f0.x + bv.x; c0.y += f1.x + bv.y; c0.z += f2.x + bv.z; c0.w += f3.x + bv.w;
        *(float4*)C0 = c0;
        float* C1 = C0 + DIM;
        float4 c1 = *(float4*)C1;
        c1.x += f0.y + bv.x; c1.y += f1.y + bv.y; c1.z += f2.y + bv.z; c1.w += f3.y + bv.w;
        *(float4*)C1 = c1;
    }
}

// ---------------- attn logits + softmax + colsum partials. grid (64, 8) ----------------
__global__ __launch_bounds__(256) void attn_softmax_kernel() {
    int lb = blockIdx.x, b = blockIdx.y;
    const float* A = g_k + ((size_t)b*LTOK + lb*64)*DIM;
    const float* Q = g_q + (size_t)b*NSLOT*DIM;
    __shared__ float As[1024], Bs[1024];
    u64 acc[4][2] = {};
    int t = threadIdx.x;
    int tm = t >> 4, tn = t & 15;
    for (int k0 = 0; k0 < 256; k0 += 16) {
        int m = t >> 2, kq = t & 3;
        float4 a4 = *(const float4*)(A + (size_t)m*DIM + k0 + kq*4);
        As[(kq*4+0)*64 + m] = a4.x;
        As[(kq*4+1)*64 + m] = a4.y;
        As[(kq*4+2)*64 + m] = a4.z;
        As[(kq*4+3)*64 + m] = a4.w;
        float4 b4 = *(const float4*)(Q + (size_t)m*DIM + k0 + kq*4);
        Bs[(kq*4+0)*64 + m] = b4.x;
        Bs[(kq*4+1)*64 + m] = b4.y;
        Bs[(kq*4+2)*64 + m] = b4.z;
        Bs[(kq*4+3)*64 + m] = b4.w;
        __syncthreads();
        #pragma unroll
        for (int kk = 0; kk < 16; kk++) {
            ulonglong2 a2 = *(ulonglong2*)(As + kk*64 + tm*4);
            float4 bb = *(float4*)(Bs + kk*64 + tn*4);
            u64 q0 = PK1(bb.x), q1 = PK1(bb.y), q2 = PK1(bb.z), q3 = PK1(bb.w);
            FMA2(acc[0][0], a2.x, q0); FMA2(acc[0][1], a2.y, q0);
            FMA2(acc[1][0], a2.x, q1); FMA2(acc[1][1], a2.y, q1);
            FMA2(acc[2][0], a2.x, q2); FMA2(acc[2][1], a2.y, q2);
            FMA2(acc[3][0], a2.x, q3); FMA2(acc[3][1], a2.y, q3);
        }
        __syncthreads();
    }
    // softmax over n per l-row; rows = tm*4 + p*2 + h
    float4 csum = {0,0,0,0};
    #pragma unroll
    for (int p = 0; p < 2; p++) {
        float2 f0 = UPK(acc[0][p]), f1 = UPK(acc[1][p]), f2 = UPK(acc[2][p]), f3 = UPK(acc[3][p]);
        #pragma unroll
        for (int h = 0; h < 2; h++) {
            float v0 = h ? f0.y : f0.x;
            float v1 = h ? f1.y : f1.x;
            float v2 = h ? f2.y : f2.x;
            float v3 = h ? f3.y : f3.x;
            float mx = fmaxf(fmaxf(v0, v1), fmaxf(v2, v3));
            #pragma unroll
            for (int m = 1; m < 16; m <<= 1) mx = fmaxf(mx, __shfl_xor_sync(0xffffffffu, mx, m));
            float e0 = expf(v0 - mx), e1 = expf(v1 - mx), e2 = expf(v2 - mx), e3 = expf(v3 - mx);
            float s = e0 + e1 + e2 + e3;
            #pragma unroll
            for (int m = 1; m < 16; m <<= 1) s += __shfl_xor_sync(0xffffffffu, s, m);
            float inv = 1.0f / s;
            float4 a;
            a.x = e0*inv + 1e-8f; a.y = e1*inv + 1e-8f; a.z = e2*inv + 1e-8f; a.w = e3*inv + 1e-8f;
            int row = tm*4 + p*2 + h;
            *(float4*)(g_attn + ((size_t)b*LTOK + lb*64 + row)*NSLOT + tn*4) = a;
            csum.x += a.x; csum.y += a.y; csum.z += a.z; csum.w += a.w;
        }
    }
    *(float4*)(As + tm*64 + tn*4) = csum;
    __syncthreads();
    if (t < 64) {
        float s = 0.f;
        #pragma unroll
        for (int r = 0; r < 16; r++) s += As[r*64 + t];
        g_colsum_part[((size_t)b*64 + lb)*NSLOT + t] = s;
    }
}

// ---------------- attn^T @ v split-K partials. grid (4, 8, 8) ----------------
__global__ __launch_bounds__(256) void gemm_c_kernel() {
    int dt = blockIdx.x, ps = blockIdx.y, b = blockIdx.z;
    const float* A = g_attn + ((size_t)b*LTOK + ps*512)*NSLOT;   // [l][slot]
    const float* B = g_v    + ((size_t)b*LTOK + ps*512)*DIM + dt*64;
    __shared__ float As[1024], Bs[1024];
    u64 acc[4][2] = {};
    int t = threadIdx.x;
    int tm = t >> 4, tn = t & 15;
    int kk0 = t >> 4, n4 = (t & 15)*4;
    for (int k0 = 0; k0 < 512; k0 += 16) {
        *(float4*)(As + kk0*64 + n4) = *(const float4*)(A + (size_t)(k0+kk0)*NSLOT + n4);
        *(float4*)(Bs + kk0*64 + n4) = *(const float4*)(B + (size_t)(k0+kk0)*DIM + n4);
        __syncthreads();
        #pragma unroll
        for (int kk = 0; kk < 16; kk++) {
            ulonglong2 a2 = *(ulonglong2*)(As + kk*64 + tm*4);   // slot pairs
            float4 bb = *(float4*)(Bs + kk*64 + tn*4);           // dims
            u64 q0 = PK1(bb.x), q1 = PK1(bb.y), q2 = PK1(bb.z), q3 = PK1(bb.w);
            FMA2(acc[0][0], a2.x, q0); FMA2(acc[0][1], a2.y, q0);
            FMA2(acc[1][0], a2.x, q1); FMA2(acc[1][1], a2.y, q1);
            FMA2(acc[2][0], a2.x, q2); FMA2(acc[2][1], a2.y, q2);
            FMA2(acc[3][0], a2.x, q3); FMA2(acc[3][1], a2.y, q3);
        }
        __syncthreads();
    }
    #pragma unroll
    for (int p = 0; p < 2; p++) {
        float2 f0 = UPK(acc[0][p]), f1 = UPK(acc[1][p]), f2 = UPK(acc[2][p]), f3 = UPK(acc[3][p]);
        int slot = tm*4 + p*2;
        float4 r0 = {f0.x, f1.x, f2.x, f3.x};
        float4 r1 = {f0.y, f1.y, f2.y, f3.y};
        *(float4*)(g_accpart + ((size_t)((ps*BATCH + b)*NSLOT) + slot  )*DIM + dt*64 + tn*4) = r0;
        *(float4*)(g_accpart + ((size_t)((ps*BATCH + b)*NSLOT) + slot+1)*DIM + dt*64 + tn*4) = r1;
    }
}

// ---------------- fused colsum + template update + LN_m. grid 8 ----------------
#define FIN_SMEM_FLOATS (16384 + 256 + 64)
__global__ __launch_bounds__(256) void finalize_kernel(const float* __restrict__ g,
                                                       const float* __restrict__ bb) {
    extern __shared__ float sm[];
    float* tv   = sm;          // 64 x 256 new template values
    float* csp  = sm + 16384;  // 4 x 64
    float* csin = sm + 16640;  // 64
    int b = blockIdx.x, t = threadIdx.x;

    // colsum
    {
        int part4 = t >> 6, n = t & 63;
        float s = 0.f;
        #pragma unroll
        for (int lb = 0; lb < 16; lb++)
            s += g_colsum_part[((size_t)b*64 + part4*16 + lb)*NSLOT + n];
        csp[part4*64 + n] = s;
    }
    __syncthreads();
    if (t < 64) {
        float tot = csp[t] + csp[64+t] + csp[128+t] + csp[192+t];
        g_colsum[b*NSLOT + t] = tot;
        csin[t] = 1.0f / tot;
    }
    __syncthreads();

    // accumulate split-K partials + residual
    for (int n = 0; n < NSLOT; n++) {
        float s = 0.f;
        #pragma unroll
        for (int p = 0; p < 8; p++)
            s += g_accpart[((size_t)((p*BATCH + b)*NSLOT) + n)*DIM + t];
        size_t idx = ((size_t)(b*NSLOT) + n)*DIM + t;
        float val = g_templates[idx] + s * csin[n];
        g_templates[idx] = val;
        tv[n*256 + t] = val;
    }
    __syncthreads();

    // LN_m from smem -> g_tbuf
    {
        int r = t >> 2, part = t & 3;
        const float* row = tv + r*256 + part*64;
        float s = 0.f, sq = 0.f;
        #pragma unroll
        for (int i = 0; i < 64; i += 4) {
            float4 v = *(const float4*)(row + i);
            s += v.x+v.y+v.z+v.w;
            sq += v.x*v.x + v.y*v.y + v.z*v.z + v.w*v.w;
        }
        s  += __shfl_xor_sync(0xffffffffu, s, 1);  s  += __shfl_xor_sync(0xffffffffu, s, 2);
        sq += __shfl_xor_sync(0xffffffffu, sq, 1); sq += __shfl_xor_sync(0xffffffffu, sq, 2);
        float mu = s * (1.0f/256.0f);
        float rs = rsqrtf(sq * (1.0f/256.0f) - mu*mu + 1e-5f);
        float* drow = g_tbuf + ((size_t)(b*NSLOT) + r)*DIM + part*64;
        #pragma unroll
        for (int i = 0; i < 64; i += 4) {
            float4 v = *(const float4*)(row + i);
            float4 gg = *(const float4*)(g + part*64 + i);
            float4 bv = *(const float4*)(bb + part*64 + i);
            float4 o;
            o.x = (v.x - mu)*rs*gg.x + bv.x;
            o.y = (v.y - mu)*rs*gg.y + bv.y;
            o.z = (v.z - mu)*rs*gg.z + bv.z;
            o.w = (v.w - mu)*rs*gg.w + bv.w;
            *(float4*)(drow + i) = o;
        }
    }
}

// ---------------- outputs ----------------
__global__ void out_templates_kernel(float* __restrict__ out) {
    int b = blockIdx.x, d = threadIdx.x;
    for (int n = 0; n < NSLOT; n++)
        out[((size_t)(b*DIM) + d)*NSLOT + n] = g_templates[((size_t)(b*NSLOT) + n)*DIM + d];
}

__global__ void out_attn_kernel(float* __restrict__ out) {
    int n = blockIdx.x, b = blockIdx.y, t = threadIdx.x;
    float inv = 1.0f / g_colsum[b*NSLOT + n];
    size_t base = (size_t)BATCH*DIM*NSLOT + ((size_t)(b*NSLOT + n))*LTOK;
    for (int k = 0; k < 16; k++) {
        int l = k*256 + t;
        out[base + l] = g_attn[((size_t)b*LTOK + l)*NSLOT + n] * inv;
    }
}

// ---------------- launch ----------------
extern "C" void kernel_launch(void* const* d_in, const int* in_sizes, int n_in,
                              void* d_out, int out_size) {
    const float* x       = (const float*)d_in[0];
    const float* tinit   = (const float*)d_in[1];
    const float* conv_w  = (const float*)d_in[2];
    const float* conv_b  = (const float*)d_in[3];
    const float* Wq      = (const float*)d_in[4];
    const float* Wk      = (const float*)d_in[5];
    const float* Wv      = (const float*)d_in[6];
    const float* ln_in_g = (const float*)d_in[7];
    const float* ln_in_b = (const float*)d_in[8];
    const float* ln_t_g  = (const float*)d_in[9];
    const float* ln_t_b  = (const float*)d_in[10];
    const float* ln_m_g  = (const float*)d_in[11];
    const float* ln_m_b  = (const float*)d_in[12];
    const float* W1      = (const float*)d_in[13];
    const float* b1      = (const float*)d_in[14];
    const float* W2      = (const float*)d_in[15];
    const float* b2      = (const float*)d_in[16];
    float* out = (float*)d_out;

    cudaFuncSetAttribute(conv_ln_kv_kernel, cudaFuncAttributeMaxDynamicSharedMemorySize,
                         CONV_SMEM_FLOATS * 4);
    cudaFuncSetAttribute(gemm_q_kernel, cudaFuncAttributeMaxDynamicSharedMemorySize, (16384+1024)*4);
    cudaFuncSetAttribute(gemm_h_kernel, cudaFuncAttributeMaxDynamicSharedMemorySize, (16384+1024)*4);
    cudaFuncSetAttribute(gemm_o_kernel, cudaFuncAttributeMaxDynamicSharedMemorySize, GEMMO_SMEM_FLOATS*4);
    cudaFuncSetAttribute(finalize_kernel, cudaFuncAttributeMaxDynamicSharedMemorySize, FIN_SMEM_FLOATS*4);

    wt_transpose_kernel<<<3456, 256>>>(conv_w);
    templates_init_kernel<<<8, 256>>>(tinit);
    conv_ln_kv_kernel<<<2048, 256, CONV_SMEM_FLOATS * 4>>>(x, conv_b, ln_in_g, ln_in_b, Wk, Wv);

    for (int it = 0; it < 6; it++) {
        gemm_q_kernel<<<dim3(4, 8), 256, (16384+1024)*4>>>(Wq, ln_t_g, ln_t_b);
        attn_softmax_kernel<<<dim3(64, 8), 256>>>();
        gemm_c_kernel<<<dim3(4, 8, 8), 256>>>();
        finalize_kernel<<<8, 256, FIN_SMEM_FLOATS*4>>>(ln_m_g, ln_m_b);
        gemm_h_kernel<<<dim3(8, 8), 256, (16384+1024)*4>>>(W1, b1);
        gemm_o_kernel<<<dim3(4, 8), 256, GEMMO_SMEM_FLOATS*4>>>(W2, b2);
    }

    out_templates_kernel<<<8, 256>>>(out);
    out_attn_kernel<<<dim3(64, 8), 256>>>(out);
}

// round 8
// speedup vs baseline: 1.9846x; 1.9846x over previous
#include <cuda_runtime.h>
#include <cuda_bf16.h>
#include <stdint.h>
#include <math.h>

#define BATCH 8
#define DIM   256
#define NSLOT 64
#define LTOK  4096

typedef unsigned long long u64;

__device__ __forceinline__ u64 PK1(float v) {
    u64 r; asm("mov.b64 %0, {%1,%1};" : "=l"(r) : "f"(v)); return r;
}
__device__ __forceinline__ void FMA2(u64& d, u64 a, u64 b) {
    asm("fma.rn.f32x2 %0, %1, %2, %0;" : "+l"(d) : "l"(a), "l"(b));
}
__device__ __forceinline__ float2 UPK(u64 v) {
    float2 f; asm("mov.b64 {%0,%1}, %2;" : "=f"(f.x), "=f"(f.y) : "l"(v)); return f;
}

// ---------------- scratch ----------------
__device__ float g_k[BATCH*LTOK*DIM];
__device__ float g_v[BATCH*LTOK*DIM];
__device__ float g_templates[BATCH*NSLOT*DIM];
__device__ float g_tbuf[BATCH*NSLOT*DIM];
__device__ float g_q[BATCH*NSLOT*DIM];
__device__ float g_attn[BATCH*LTOK*NSLOT];
__device__ float g_colsum_part[BATCH*64*NSLOT];
__device__ float g_colsum[BATCH*NSLOT];
__device__ float g_accpart[8*BATCH*NSLOT*DIM];
__device__ float g_hidden[BATCH*NSLOT*512];
// bf16 split operands
__device__ __nv_bfloat16 g_xh[36799488];      // x channel-last hi [b][d][h][w][c]
__device__ __nv_bfloat16 g_xl[36799488];
__device__ __nv_bfloat16 g_cwh[27*32768];     // conv W per tap [k=128][n=256]
__device__ __nv_bfloat16 g_cwl[27*32768];
__device__ __nv_bfloat16 g_kvh[256*512];      // [k=256][ Wk(256) | Wv(256) ]
__device__ __nv_bfloat16 g_kvl[256*512];
__device__ __nv_bfloat16 g_toksh[32768*256];  // LN'd tokens hi
__device__ __nv_bfloat16 g_toksl[32768*256];

__device__ __forceinline__ float gelu_exact(float v) {
    return 0.5f * v * (1.0f + erff(v * 0.70710678118654752f));
}

// ========== mma.sync helpers ==========
__device__ __forceinline__ uint32_t smem_u32(const void* p) {
    uint32_t a;
    asm("{ .reg .u64 t; cvta.to.shared.u64 t, %1; cvt.u32.u64 %0, t; }" : "=r"(a) : "l"(p));
    return a;
}
__device__ __forceinline__ void ldsm_x4(uint32_t* r, uint32_t addr) {
    asm volatile("ldmatrix.sync.aligned.m8n8.x4.shared.b16 {%0,%1,%2,%3}, [%4];"
        : "=r"(r[0]), "=r"(r[1]), "=r"(r[2]), "=r"(r[3]) : "r"(addr));
}
__device__ __forceinline__ void ldsm_x4_t(uint32_t* r, uint32_t addr) {
    asm volatile("ldmatrix.sync.aligned.m8n8.x4.trans.shared.b16 {%0,%1,%2,%3}, [%4];"
        : "=r"(r[0]), "=r"(r[1]), "=r"(r[2]), "=r"(r[3]) : "r"(addr));
}
__device__ __forceinline__ void mma_bf16(float* d, const uint32_t* a, const uint32_t* b) {
    asm volatile("mma.sync.aligned.m16n8k16.row.col.f32.bf16.bf16.f32 "
        "{%0,%1,%2,%3}, {%4,%5,%6,%7}, {%8,%9}, {%0,%1,%2,%3};"
        : "+f"(d[0]), "+f"(d[1]), "+f"(d[2]), "+f"(d[3])
        : "r"(a[0]), "r"(a[1]), "r"(a[2]), "r"(a[3]), "r"(b[0]), "r"(b[1]));
}

// 128x256 += A(128x128, pitch 272B) x B(128k x 256n, pitch 528B); 3-term bf16 split.
// 16 warps: wm = wid>>2 (m tile 32), wn = wid&3 (n tile 64).
__device__ __forceinline__ void mma_chunk(
    uint32_t sAh, uint32_t sAl, uint32_t sBh, uint32_t sBl,
    float d[2][8][4], int wm, int wn, int lane)
{
    uint32_t aoff0 = (uint32_t)((wm*32 + (lane & 15))*272 + (lane >> 4)*16);
    uint32_t boff0 = (uint32_t)((lane & 15)*528 + (wn*64 + (lane >> 4)*8)*2);
    #pragma unroll
    for (int kk = 0; kk < 8; kk++) {
        uint32_t ah[8], al[8], bb[16];
        uint32_t ao = aoff0 + kk*32;
        ldsm_x4(ah,     sAh + ao);
        ldsm_x4(ah + 4, sAh + ao + 4352);
        ldsm_x4(al,     sAl + ao);
        ldsm_x4(al + 4, sAl + ao + 4352);
        uint32_t bo = boff0 + kk*8448;
        #pragma unroll
        for (int jj = 0; jj < 4; jj++) ldsm_x4_t(bb + jj*4, sBh + bo + jj*32);
        #pragma unroll
        for (int mi = 0; mi < 2; mi++) {
            #pragma unroll
            for (int j = 0; j < 8; j++) {
                const uint32_t* bf = bb + (j >> 1)*4 + (j & 1)*2;
                mma_bf16(d[mi][j], mi ? ah + 4 : ah, bf);
                mma_bf16(d[mi][j], mi ? al + 4 : al, bf);
            }
        }
        #pragma unroll
        for (int jj = 0; jj < 4; jj++) ldsm_x4_t(bb + jj*4, sBl + bo + jj*32);
        #pragma unroll
        for (int mi = 0; mi < 2; mi++) {
            #pragma unroll
            for (int j = 0; j < 8; j++) {
                const uint32_t* bf = bb + (j >> 1)*4 + (j & 1)*2;
                mma_bf16(d[mi][j], mi ? ah + 4 : ah, bf);
            }
        }
    }
}

// ---------------- prep kernels ----------------
__global__ void templates_init_kernel(const float* __restrict__ tinit) {
    int b = blockIdx.x, t = threadIdx.x;
    for (int n = 0; n < NSLOT; n++)
        g_templates[(b*NSLOT + n)*DIM + t] = tinit[n*DIM + t];
}

__global__ __launch_bounds__(256) void xsplit_kernel(const float* __restrict__ x) {
    __shared__ float st[128*33];
    int bid = blockIdx.x; int b = bid / 1089; int rem = bid % 1089; int d = rem / 33, h = rem % 33;
    int t = threadIdx.x, warp = t >> 5, lane = t & 31;
    const float* xb = x + ((((size_t)b*128)*33 + d)*33 + h)*33;
    for (int c = warp; c < 128; c += 8) {
        const float* src = xb + (size_t)c*35937;
        st[c*33 + lane] = src[lane];
        if (lane == 0) st[c*33 + 32] = src[32];   // FIX: element 32
    }
    __syncthreads();
    size_t ob = ((((size_t)b*33 + d)*33 + h)*33)*128;
    for (int i = t; i < 33*128; i += 256) {
        int w = i >> 7, c = i & 127;
        float v = st[c*33 + w];
        __nv_bfloat16 hi = __float2bfloat16(v);
        g_xh[ob + (size_t)w*128 + c] = hi;
        g_xl[ob + (size_t)w*128 + c] = __float2bfloat16(v - __bfloat162float(hi));
    }
}

__global__ void cwsplit_kernel(const float* __restrict__ cw) {
    int idx = blockIdx.x*256 + threadIdx.x;     // grid 3456
    int tap = idx >> 15, r = idx & 32767;
    int k = r >> 8, n = r & 255;
    float v = cw[(size_t)n*3456 + k*27 + tap];
    __nv_bfloat16 hi = __float2bfloat16(v);
    g_cwh[idx] = hi;
    g_cwl[idx] = __float2bfloat16(v - __bfloat162float(hi));
}

__global__ void kvsplit_kernel(const float* __restrict__ Wk, const float* __restrict__ Wv) {
    int idx = blockIdx.x*256 + threadIdx.x;     // grid 512
    int k = idx >> 9, c512 = idx & 511;
    int mat = c512 >> 8, col = c512 & 255;
    const float* W = mat ? Wv : Wk;
    float v = W[(size_t)k*256 + col];
    __nv_bfloat16 hi = __float2bfloat16(v);
    g_kvh[idx] = hi;
    g_kvl[idx] = __float2bfloat16(v - __bfloat162float(hi));
}

// ---------------- conv (implicit GEMM via mma.sync) + bias + ReLU + LN ----------------
#define CMM_SMEM 204800
__global__ __launch_bounds__(512, 1) void conv_mma_kernel(
    const float* __restrict__ convb, const float* __restrict__ lng, const float* __restrict__ lnb)
{
    extern __shared__ char sm[];
    uint32_t sb = smem_u32(sm);
    const uint32_t oAh = 0, oAl = 34816, oBh = 69632, oBl = 137216;
    int t = threadIdx.x, lane = t & 31, wid = t >> 5;
    int wm = wid >> 2, wn = wid & 3;
    int bx = blockIdx.x; int b = bx >> 5, xd = (bx >> 1) & 15, half = bx & 1;

    float d[2][8][4];
    #pragma unroll
    for (int i = 0; i < 2; i++)
        #pragma unroll
        for (int j = 0; j < 8; j++)
            #pragma unroll
            for (int c = 0; c < 4; c++) d[i][j][c] = 0.f;

    int m = t >> 2, q = t & 3;
    int xhl = m >> 4, xw = m & 15;

    for (int tap = 0; tap < 27; tap++) {
        int kd = tap/9, r9 = tap%9, kh = r9/3, kw = r9%3;
        {
            size_t xi = ((((size_t)(b*33) + 2*xd + kd)*33 + 2*(half*8 + xhl) + kh)*33 + 2*xw + kw)*128 + q*32;
            const uint4* shi = (const uint4*)(g_xh + xi);
            const uint4* slo = (const uint4*)(g_xl + xi);
            char* dh = sm + oAh + m*272 + q*64;
            char* dl = sm + oAl + m*272 + q*64;
            #pragma unroll
            for (int j = 0; j < 4; j++) {
                *(uint4*)(dh + j*16) = shi[j];
                *(uint4*)(dl + j*16) = slo[j];
            }
        }
        {
            const uint4* s1 = (const uint4*)(g_cwh + tap*32768);
            const uint4* s2 = (const uint4*)(g_cwl + tap*32768);
            #pragma unroll
            for (int it = 0; it < 8; it++) {
                int i = t + it*512;
                int row = i >> 5, seg = i & 31;
                *(uint4*)(sm + oBh + row*528 + seg*16) = s1[i];
                *(uint4*)(sm + oBl + row*528 + seg*16) = s2[i];
            }
        }
        __syncthreads();
        mma_chunk(sb + oAh, sb + oAl, sb + oBh, sb + oBl, d, wm, wn, lane);
        __syncthreads();
    }

    // stage fp32 accum to smem, pitch 264 floats
    float* stg = (float*)sm;
    {
        int r0 = wm*32 + (lane >> 2);
        int c0 = wn*64 + (lane & 3)*2;
        #pragma unroll
        for (int mi = 0; mi < 2; mi++)
            #pragma unroll
            for (int j = 0; j < 8; j++) {
                int rr = r0 + mi*16, cc = c0 + j*8;
                *(float2*)(stg + (size_t)rr*264 + cc)     = make_float2(d[mi][j][0], d[mi][j][1]);
                *(float2*)(stg + (size_t)(rr+8)*264 + cc) = make_float2(d[mi][j][2], d[mi][j][3]);
            }
    }
    __syncthreads();

    {
        int tok = t >> 2, q2 = t & 3;
        const float* src = stg + (size_t)tok*264 + q2*64;
        float z[64];
        float s = 0.f, sq = 0.f;
        #pragma unroll
        for (int i = 0; i < 64; i++) {
            float v = fmaxf(src[i] + convb[q2*64 + i], 0.f);
            z[i] = v; s += v; sq += v*v;
        }
        s  += __shfl_xor_sync(0xffffffffu, s, 1);  s  += __shfl_xor_sync(0xffffffffu, s, 2);
        sq += __shfl_xor_sync(0xffffffffu, sq, 1); sq += __shfl_xor_sync(0xffffffffu, sq, 2);
        float mu = s * (1.f/256.f);
        float rs = rsqrtf(sq * (1.f/256.f) - mu*mu + 1e-5f);
        int l = (xd*16 + half*8 + (tok >> 4))*16 + (tok & 15);
        size_t tg = ((size_t)b*4096 + l)*256 + q2*64;
        #pragma unroll
        for (int i = 0; i < 64; i += 2) {
            int ch = q2*64 + i;
            float v0 = (z[i]   - mu)*rs*lng[ch]   + lnb[ch];
            float v1 = (z[i+1] - mu)*rs*lng[ch+1] + lnb[ch+1];
            __nv_bfloat16 h0 = __float2bfloat16(v0), h1 = __float2bfloat16(v1);
            __nv_bfloat162 hh; hh.x = h0; hh.y = h1;
            __nv_bfloat162 ll;
            ll.x = __float2bfloat16(v0 - __bfloat162float(h0));
            ll.y = __float2bfloat16(v1 - __bfloat162float(h1));
            *(__nv_bfloat162*)(g_toksh + tg + i) = hh;
            *(__nv_bfloat162*)(g_toksl + tg + i) = ll;
        }
    }
}

// ---------------- K/V projection via mma.sync ----------------
__global__ __launch_bounds__(512, 1) void kv_mma_kernel() {
    extern __shared__ char sm[];
    uint32_t sb = smem_u32(sm);
    const uint32_t oAh = 0, oAl = 34816, oBh = 69632, oBl = 137216;
    int t = threadIdx.x, lane = t & 31, wid = t >> 5;
    int wm = wid >> 2, wn = wid & 3;
    int nhalf = blockIdx.x & 1, chunk = blockIdx.x >> 1;

    float d[2][8][4];
    #pragma unroll
    for (int i = 0; i < 2; i++)
        #pragma unroll
        for (int j = 0; j < 8; j++)
            #pragma unroll
            for (int c = 0; c < 4; c++) d[i][j][c] = 0.f;

    int m = t >> 2, q = t & 3;
    for (int kc = 0; kc < 2; kc++) {
        {
            size_t ti = ((size_t)(chunk*128 + m))*256 + kc*128 + q*32;
            const uint4* shi = (const uint4*)(g_toksh + ti);
            const uint4* slo = (const uint4*)(g_toksl + ti);
            char* dh = sm + oAh + m*272 + q*64;
            char* dl = sm + oAl + m*272 + q*64;
            #pragma unroll
            for (int j = 0; j < 4; j++) {
                *(uint4*)(dh + j*16) = shi[j];
                *(uint4*)(dl + j*16) = slo[j];
            }
        }
        {
            // FIX: full 256-column B tile (8 iters, seg 0..31)
            #pragma unroll
            for (int it = 0; it < 8; it++) {
                int i = t + it*512;
                int row = i >> 5, seg = i & 31;
                size_t off = (size_t)(kc*128 + row)*512 + nhalf*256 + seg*8;
                *(uint4*)(sm + oBh + row*528 + seg*16) = *(const uint4*)(g_kvh + off);
                *(uint4*)(sm + oBl + row*528 + seg*16) = *(const uint4*)(g_kvl + off);
            }
        }
        __syncthreads();
        mma_chunk(sb + oAh, sb + oAl, sb + oBh, sb + oBl, d, wm, wn, lane);
        __syncthreads();
    }

    float* dst = nhalf ? g_v : g_k;
    int r0 = wm*32 + (lane >> 2);
    int c0 = wn*64 + (lane & 3)*2;
    #pragma unroll
    for (int mi = 0; mi < 2; mi++)
        #pragma unroll
        for (int j = 0; j < 8; j++) {
            int rr = r0 + mi*16, cc = c0 + j*8;
            size_t tok = (size_t)chunk*128 + rr;
            *(float2*)(dst + tok*256 + cc)       = make_float2(d[mi][j][0], d[mi][j][1]);
            *(float2*)(dst + (tok+8)*256 + cc)   = make_float2(d[mi][j][2], d[mi][j][3]);
        }
}

// ---------------- iteration-loop kernels (proven, unchanged) ----------------
__global__ __launch_bounds__(256) void gemm_q_kernel(
    const float* __restrict__ Wq, const float* __restrict__ lng, const float* __restrict__ lnb)
{
    extern __shared__ float smf[];
    float* Af = smf; float* Bs = smf + 16384;
    int b = blockIdx.y; int nc = blockIdx.x * 64;
    int t = threadIdx.x;
    {
        int r = t >> 2, part = t & 3;
        const float* row = g_templates + ((size_t)(b*NSLOT) + r)*DIM + part*64;
        float s = 0.f, sq = 0.f;
        #pragma unroll
        for (int i = 0; i < 64; i += 4) {
            float4 v = *(const float4*)(row + i);
            s += v.x+v.y+v.z+v.w;
            sq += v.x*v.x + v.y*v.y + v.z*v.z + v.w*v.w;
        }
        s  += __shfl_xor_sync(0xffffffffu, s, 1);  s  += __shfl_xor_sync(0xffffffffu, s, 2);
        sq += __shfl_xor_sync(0xffffffffu, sq, 1); sq += __shfl_xor_sync(0xffffffffu, sq, 2);
        float mu = s * (1.0f/256.0f);
        float rs = rsqrtf(sq * (1.0f/256.0f) - mu*mu + 1e-5f);
        #pragma unroll
        for (int i = 0; i < 64; i += 4) {
            float4 v = *(const float4*)(row + i);
            float4 gg = *(const float4*)(lng + part*64 + i);
            float4 bv = *(const float4*)(lnb + part*64 + i);
            Af[(part*64+i+0)*64 + r] = (v.x - mu)*rs*gg.x + bv.x;
            Af[(part*64+i+1)*64 + r] = (v.y - mu)*rs*gg.y + bv.y;
            Af[(part*64+i+2)*64 + r] = (v.z - mu)*rs*gg.z + bv.z;
            Af[(part*64+i+3)*64 + r] = (v.w - mu)*rs*gg.w + bv.w;
        }
    }
    __syncthreads();
    int tm = t >> 4, tn = t & 15;
    u64 acc[4][2] = {};
    int kk0 = t >> 4, n4 = (t & 15)*4;
    for (int k0 = 0; k0 < 256; k0 += 16) {
        *(float4*)(Bs + kk0*64 + n4) = *(const float4*)(Wq + (size_t)(k0+kk0)*256 + nc + n4);
        __syncthreads();
        #pragma unroll
        for (int kk = 0; kk < 16; kk++) {
            ulonglong2 a2 = *(ulonglong2*)(Af + (k0+kk)*64 + tm*4);
            float4 bb = *(float4*)(Bs + kk*64 + tn*4);
            u64 q0 = PK1(bb.x), q1 = PK1(bb.y), q2 = PK1(bb.z), q3 = PK1(bb.w);
            FMA2(acc[0][0], a2.x, q0); FMA2(acc[0][1], a2.y, q0);
            FMA2(acc[1][0], a2.x, q1); FMA2(acc[1][1], a2.y, q1);
            FMA2(acc[2][0], a2.x, q2); FMA2(acc[2][1], a2.y, q2);
            FMA2(acc[3][0], a2.x, q3); FMA2(acc[3][1], a2.y, q3);
        }
        __syncthreads();
    }
    const float scale = 0.0625f;
    #pragma unroll
    for (int p = 0; p < 2; p++) {
        float2 f0 = UPK(acc[0][p]), f1 = UPK(acc[1][p]), f2 = UPK(acc[2][p]), f3 = UPK(acc[3][p]);
        float4 r0 = {f0.x*scale, f1.x*scale, f2.x*scale, f3.x*scale};
        float4 r1 = {f0.y*scale, f1.y*scale, f2.y*scale, f3.y*scale};
        int mm = tm*4 + p*2;
        *(float4*)(g_q + ((size_t)(b*NSLOT) + mm  )*DIM + nc + tn*4) = r0;
        *(float4*)(g_q + ((size_t)(b*NSLOT) + mm+1)*DIM + nc + tn*4) = r1;
    }
}

__global__ __launch_bounds__(256) void gemm_h_kernel(const float* __restrict__ W1,
                                                     const float* __restrict__ b1)
{
    extern __shared__ float smf[];
    float* Af = smf; float* Bs = smf + 16384;
    int b = blockIdx.y; int nc = blockIdx.x * 64;
    int t = threadIdx.x;
    {
        int r = t >> 2, part = t & 3;
        const float* row = g_tbuf + ((size_t)(b*NSLOT) + r)*DIM + part*64;
        #pragma unroll
        for (int i = 0; i < 64; i += 4) {
            float4 v = *(const float4*)(row + i);
            Af[(part*64+i+0)*64 + r] = v.x;
            Af[(part*64+i+1)*64 + r] = v.y;
            Af[(part*64+i+2)*64 + r] = v.z;
            Af[(part*64+i+3)*64 + r] = v.w;
        }
    }
    __syncthreads();
    int tm = t >> 4, tn = t & 15;
    u64 acc[4][2] = {};
    int kk0 = t >> 4, n4 = (t & 15)*4;
    for (int k0 = 0; k0 < 256; k0 += 16) {
        *(float4*)(Bs + kk0*64 + n4) = *(const float4*)(W1 + (size_t)(k0+kk0)*512 + nc + n4);
        __syncthreads();
        #pragma unroll
        for (int kk = 0; kk < 16; kk++) {
            ulonglong2 a2 = *(ulonglong2*)(Af + (k0+kk)*64 + tm*4);
            float4 bb = *(float4*)(Bs + kk*64 + tn*4);
            u64 q0 = PK1(bb.x), q1 = PK1(bb.y), q2 = PK1(bb.z), q3 = PK1(bb.w);
            FMA2(acc[0][0], a2.x, q0); FMA2(acc[0][1], a2.y, q0);
            FMA2(acc[1][0], a2.x, q1); FMA2(acc[1][1], a2.y, q1);
            FMA2(acc[2][0], a2.x, q2); FMA2(acc[2][1], a2.y, q2);
            FMA2(acc[3][0], a2.x, q3); FMA2(acc[3][1], a2.y, q3);
        }
        __syncthreads();
    }
    float4 bv = *(const float4*)(b1 + nc + tn*4);
    #pragma unroll
    for (int p = 0; p < 2; p++) {
        float2 f0 = UPK(acc[0][p]), f1 = UPK(acc[1][p]), f2 = UPK(acc[2][p]), f3 = UPK(acc[3][p]);
        float4 r0 = {gelu_exact(f0.x+bv.x), gelu_exact(f1.x+bv.y), gelu_exact(f2.x+bv.z), gelu_exact(f3.x+bv.w)};
        float4 r1 = {gelu_exact(f0.y+bv.x), gelu_exact(f1.y+bv.y), gelu_exact(f2.y+bv.z), gelu_exact(f3.y+bv.w)};
        int mm = tm*4 + p*2;
        *(float4*)(g_hidden + ((size_t)(b*NSLOT) + mm  )*512 + nc + tn*4) = r0;
        *(float4*)(g_hidden + ((size_t)(b*NSLOT) + mm+1)*512 + nc + tn*4) = r1;
    }
}

#define GEMMO_SMEM_FLOATS (32768 + 1024)
__global__ __launch_bounds__(256) void gemm_o_kernel(const float* __restrict__ W2,
                                                     const float* __restrict__ b2)
{
    extern __shared__ float smf[];
    float* Af = smf; float* Bs = smf + 32768;
    int b = blockIdx.y; int nc = blockIdx.x * 64;
    int t = threadIdx.x;
    {
        int r = t >> 2, part = t & 3;
        const float* row = g_hidden + ((size_t)(b*NSLOT) + r)*512 + part*128;
        #pragma unroll
        for (int i = 0; i < 128; i += 4) {
            float4 v = *(const float4*)(row + i);
            Af[(part*128+i+0)*64 + r] = v.x;
            Af[(part*128+i+1)*64 + r] = v.y;
            Af[(part*128+i+2)*64 + r] = v.z;
            Af[(part*128+i+3)*64 + r] = v.w;
        }
    }
    __syncthreads();
    int tm = t >> 4, tn = t & 15;
    u64 acc[4][2] = {};
    int kk0 = t >> 4, n4 = (t & 15)*4;
    for (int k0 = 0; k0 < 512; k0 += 16) {
        *(float4*)(Bs + kk0*64 + n4) = *(const float4*)(W2 + (size_t)(k0+kk0)*256 + nc + n4);
        __syncthreads();
        #pragma unroll
        for (int kk = 0; kk < 16; kk++) {
            ulonglong2 a2 = *(ulonglong2*)(Af + (k0+kk)*64 + tm*4);
            float4 bb = *(float4*)(Bs + kk*64 + tn*4);
            u64 q0 = PK1(bb.x), q1 = PK1(bb.y), q2 = PK1(bb.z), q3 = PK1(bb.w);
            FMA2(acc[0][0], a2.x, q0); FMA2(acc[0][1], a2.y, q0);
            FMA2(acc[1][0], a2.x, q1); FMA2(acc[1][1], a2.y, q1);
            FMA2(acc[2][0], a2.x, q2); FMA2(acc[2][1], a2.y, q2);
            FMA2(acc[3][0], a2.x, q3); FMA2(acc[3][1], a2.y, q3);
        }
        __syncthreads();
    }
    float4 bv = *(const float4*)(b2 + nc + tn*4);
    #pragma unroll
    for (int p = 0; p < 2; p++) {
        float2 f0 = UPK(acc[0][p]), f1 = UPK(acc[1][p]), f2 = UPK(acc[2][p]), f3 = UPK(acc[3][p]);
        int mm = tm*4 + p*2;
        float* C0 = g_templates + ((size_t)(b*NSLOT) + mm)*DIM + nc + tn*4;
        float4 c0 = *(float4*)C0;
        c0.x += f0.x + bv.x; c0.y += f1.x + bv.y; c0.z += f2.x + bv.z; c0.w += f3.x + bv.w;
        *(float4*)C0 = c0;
        float* C1 = C0 + DIM;
        float4 c1 = *(float4*)C1;
        c1.x += f0.y + bv.x; c1.y += f1.y + bv.y; c1.z += f2.y + bv.z; c1.w += f3.y + bv.w;
        *(float4*)C1 = c1;
    }
}

__global__ __launch_bounds__(256) void attn_softmax_kernel() {
    int lb = blockIdx.x, b = blockIdx.y;
    const float* A = g_k + ((size_t)b*LTOK + lb*64)*DIM;
    const float* Q = g_q + (size_t)b*NSLOT*DIM;
    __shared__ float As[1024], Bs[1024];
    u64 acc[4][2] = {};
    int t = threadIdx.x;
    int tm = t >> 4, tn = t & 15;
    for (int k0 = 0; k0 < 256; k0 += 16) {
        int mq = t >> 2, kq = t & 3;
        float4 a4 = *(const float4*)(A + (size_t)mq*DIM + k0 + kq*4);
        As[(kq*4+0)*64 + mq] = a4.x;
        As[(kq*4+1)*64 + mq] = a4.y;
        As[(kq*4+2)*64 + mq] = a4.z;
        As[(kq*4+3)*64 + mq] = a4.w;
        float4 b4 = *(const float4*)(Q + (size_t)mq*DIM + k0 + kq*4);
        Bs[(kq*4+0)*64 + mq] = b4.x;
        Bs[(kq*4+1)*64 + mq] = b4.y;
        Bs[(kq*4+2)*64 + mq] = b4.z;
        Bs[(kq*4+3)*64 + mq] = b4.w;
        __syncthreads();
        #pragma unroll
        for (int kk = 0; kk < 16; kk++) {
            ulonglong2 a2 = *(ulonglong2*)(As + kk*64 + tm*4);
            float4 bb = *(float4*)(Bs + kk*64 + tn*4);
            u64 q0 = PK1(bb.x), q1 = PK1(bb.y), q2 = PK1(bb.z), q3 = PK1(bb.w);
            FMA2(acc[0][0], a2.x, q0); FMA2(acc[0][1], a2.y, q0);
            FMA2(acc[1][0], a2.x, q1); FMA2(acc[1][1], a2.y, q1);
            FMA2(acc[2][0], a2.x, q2); FMA2(acc[2][1], a2.y, q2);
            FMA2(acc[3][0], a2.x, q3); FMA2(acc[3][1], a2.y, q3);
        }
        __syncthreads();
    }
    float4 csum = {0,0,0,0};
    #pragma unroll
    for (int p = 0; p < 2; p++) {
        float2 f0 = UPK(acc[0][p]), f1 = UPK(acc[1][p]), f2 = UPK(acc[2][p]), f3 = UPK(acc[3][p]);
        #pragma unroll
        for (int h = 0; h < 2; h++) {
            float v0 = h ? f0.y : f0.x;
            float v1 = h ? f1.y : f1.x;
            float v2 = h ? f2.y : f2.x;
            float v3 = h ? f3.y : f3.x;
            float mx = fmaxf(fmaxf(v0, v1), fmaxf(v2, v3));
            #pragma unroll
            for (int mk = 1; mk < 16; mk <<= 1) mx = fmaxf(mx, __shfl_xor_sync(0xffffffffu, mx, mk));
            float e0 = expf(v0 - mx), e1 = expf(v1 - mx), e2 = expf(v2 - mx), e3 = expf(v3 - mx);
            float s = e0 + e1 + e2 + e3;
            #pragma unroll
            for (int mk = 1; mk < 16; mk <<= 1) s += __shfl_xor_sync(0xffffffffu, s, mk);
            float inv = 1.0f / s;
            float4 a;
            a.x = e0*inv + 1e-8f; a.y = e1*inv + 1e-8f; a.z = e2*inv + 1e-8f; a.w = e3*inv + 1e-8f;
            int row = tm*4 + p*2 + h;
            *(float4*)(g_attn + ((size_t)b*LTOK + lb*64 + row)*NSLOT + tn*4) = a;
            csum.x += a.x; csum.y += a.y; csum.z += a.z; csum.w += a.w;
        }
    }
    *(float4*)(As + tm*64 + tn*4) = csum;
    __syncthreads();
    if (t < 64) {
        float s = 0.f;
        #pragma unroll
        for (int r = 0; r < 16; r++) s += As[r*64 + t];
        g_colsum_part[((size_t)b*64 + lb)*NSLOT + t] = s;
    }
}

__global__ __launch_bounds__(256) void gemm_c_kernel() {
    int dt = blockIdx.x, ps = blockIdx.y, b = blockIdx.z;
    const float* A = g_attn + ((size_t)b*LTOK + ps*512)*NSLOT;
    const float* B = g_v    + ((size_t)b*LTOK + ps*512)*DIM + dt*64;
    __shared__ float As[1024], Bs[1024];
    u64 acc[4][2] = {};
    int t = threadIdx.x;
    int tm = t >> 4, tn = t & 15;
    int kk0 = t >> 4, n4 = (t & 15)*4;
    for (int k0 = 0; k0 < 512; k0 += 16) {
        *(float4*)(As + kk0*64 + n4) = *(const float4*)(A + (size_t)(k0+kk0)*NSLOT + n4);
        *(float4*)(Bs + kk0*64 + n4) = *(const float4*)(B + (size_t)(k0+kk0)*DIM + n4);
        __syncthreads();
        #pragma unroll
        for (int kk = 0; kk < 16; kk++) {
            ulonglong2 a2 = *(ulonglong2*)(As + kk*64 + tm*4);
            float4 bb = *(float4*)(Bs + kk*64 + tn*4);
            u64 q0 = PK1(bb.x), q1 = PK1(bb.y), q2 = PK1(bb.z), q3 = PK1(bb.w);
            FMA2(acc[0][0], a2.x, q0); FMA2(acc[0][1], a2.y, q0);
            FMA2(acc[1][0], a2.x, q1); FMA2(acc[1][1], a2.y, q1);
            FMA2(acc[2][0], a2.x, q2); FMA2(acc[2][1], a2.y, q2);
            FMA2(acc[3][0], a2.x, q3); FMA2(acc[3][1], a2.y, q3);
        }
        __syncthreads();
    }
    #pragma unroll
    for (int p = 0; p < 2; p++) {
        float2 f0 = UPK(acc[0][p]), f1 = UPK(acc[1][p]), f2 = UPK(acc[2][p]), f3 = UPK(acc[3][p]);
        int slot = tm*4 + p*2;
        float4 r0 = {f0.x, f1.x, f2.x, f3.x};
        float4 r1 = {f0.y, f1.y, f2.y, f3.y};
        *(float4*)(g_accpart + ((size_t)((ps*BATCH + b)*NSLOT) + slot  )*DIM + dt*64 + tn*4) = r0;
        *(float4*)(g_accpart + ((size_t)((ps*BATCH + b)*NSLOT) + slot+1)*DIM + dt*64 + tn*4) = r1;
    }
}

#define FIN_SMEM_FLOATS (16384 + 256 + 64)
__global__ __launch_bounds__(256) void finalize_kernel(const float* __restrict__ g,
                                                       const float* __restrict__ bb) {
    extern __shared__ float smf[];
    float* tv   = smf;
    float* csp  = smf + 16384;
    float* csin = smf + 16640;
    int b = blockIdx.x, t = threadIdx.x;
    {
        int part4 = t >> 6, n = t & 63;
        float s = 0.f;
        #pragma unroll
        for (int lb = 0; lb < 16; lb++)
            s += g_colsum_part[((size_t)b*64 + part4*16 + lb)*NSLOT + n];
        csp[part4*64 + n] = s;
    }
    __syncthreads();
    if (t < 64) {
        float tot = csp[t] + csp[64+t] + csp[128+t] + csp[192+t];
        g_colsum[b*NSLOT + t] = tot;
        csin[t] = 1.0f / tot;
    }
    __syncthreads();
    for (int n = 0; n < NSLOT; n++) {
        float s = 0.f;
        #pragma unroll
        for (int p = 0; p < 8; p++)
            s += g_accpart[((size_t)((p*BATCH + b)*NSLOT) + n)*DIM + t];
        size_t idx = ((size_t)(b*NSLOT) + n)*DIM + t;
        float val = g_templates[idx] + s * csin[n];
        g_templates[idx] = val;
        tv[n*256 + t] = val;
    }
    __syncthreads();
    {
        int r = t >> 2, part = t & 3;
        const float* row = tv + r*256 + part*64;
        float s = 0.f, sq = 0.f;
        #pragma unroll
        for (int i = 0; i < 64; i += 4) {
            float4 v = *(const float4*)(row + i);
            s += v.x+v.y+v.z+v.w;
            sq += v.x*v.x + v.y*v.y + v.z*v.z + v.w*v.w;
        }
        s  += __shfl_xor_sync(0xffffffffu, s, 1);  s  += __shfl_xor_sync(0xffffffffu, s, 2);
        sq += __shfl_xor_sync(0xffffffffu, sq, 1); sq += __shfl_xor_sync(0xffffffffu, sq, 2);
        float mu = s * (1.0f/256.0f);
        float rs = rsqrtf(sq * (1.0f/256.0f) - mu*mu + 1e-5f);
        float* drow = g_tbuf + ((size_t)(b*NSLOT) + r)*DIM + part*64;
        #pragma unroll
        for (int i = 0; i < 64; i += 4) {
            float4 v = *(const float4*)(row + i);
            float4 gg = *(const float4*)(g + part*64 + i);
            float4 bv = *(const float4*)(bb + part*64 + i);
            float4 o;
            o.x = (v.x - mu)*rs*gg.x + bv.x;
            o.y = (v.y - mu)*rs*gg.y + bv.y;
            o.z = (v.z - mu)*rs*gg.z + bv.z;
            o.w = (v.w - mu)*rs*gg.w + bv.w;
            *(float4*)(drow + i) = o;
        }
    }
}

__global__ void out_templates_kernel(float* __restrict__ out) {
    int b = blockIdx.x, d = threadIdx.x;
    for (int n = 0; n < NSLOT; n++)
        out[((size_t)(b*DIM) + d)*NSLOT + n] = g_templates[((size_t)(b*NSLOT) + n)*DIM + d];
}

__global__ void out_attn_kernel(float* __restrict__ out) {
    int n = blockIdx.x, b = blockIdx.y, t = threadIdx.x;
    float inv = 1.0f / g_colsum[b*NSLOT + n];
    size_t base = (size_t)BATCH*DIM*NSLOT + ((size_t)(b*NSLOT + n))*LTOK;
    for (int k = 0; k < 16; k++) {
        int l = k*256 + t;
        out[base + l] = g_attn[((size_t)b*LTOK + l)*NSLOT + n] * inv;
    }
}

// ---------------- launch ----------------
extern "C" void kernel_launch(void* const* d_in, const int* in_sizes, int n_in,
                              void* d_out, int out_size) {
    const float* x       = (const float*)d_in[0];
    const float* tinit   = (const float*)d_in[1];
    const float* conv_w  = (const float*)d_in[2];
    const float* conv_b  = (const float*)d_in[3];
    const float* Wq      = (const float*)d_in[4];
    const float* Wk      = (const float*)d_in[5];
    const float* Wv      = (const float*)d_in[6];
    const float* ln_in_g = (const float*)d_in[7];
    const float* ln_in_b = (const float*)d_in[8];
    const float* ln_t_g  = (const float*)d_in[9];
    const float* ln_t_b  = (const float*)d_in[10];
    const float* ln_m_g  = (const float*)d_in[11];
    const float* ln_m_b  = (const float*)d_in[12];
    const float* W1      = (const float*)d_in[13];
    const float* b1      = (const float*)d_in[14];
    const float* W2      = (const float*)d_in[15];
    const float* b2      = (const float*)d_in[16];
    float* out = (float*)d_out;

    cudaFuncSetAttribute(conv_mma_kernel, cudaFuncAttributeMaxDynamicSharedMemorySize, CMM_SMEM);
    cudaFuncSetAttribute(kv_mma_kernel, cudaFuncAttributeMaxDynamicSharedMemorySize, CMM_SMEM);
    cudaFuncSetAttribute(gemm_q_kernel, cudaFuncAttributeMaxDynamicSharedMemorySize, (16384+1024)*4);
    cudaFuncSetAttribute(gemm_h_kernel, cudaFuncAttributeMaxDynamicSharedMemorySize, (16384+1024)*4);
    cudaFuncSetAttribute(gemm_o_kernel, cudaFuncAttributeMaxDynamicSharedMemorySize, GEMMO_SMEM_FLOATS*4);
    cudaFuncSetAttribute(finalize_kernel, cudaFuncAttributeMaxDynamicSharedMemorySize, FIN_SMEM_FLOATS*4);

    templates_init_kernel<<<8, 256>>>(tinit);
    xsplit_kernel<<<8*33*33, 256>>>(x);
    cwsplit_kernel<<<3456, 256>>>(conv_w);
    kvsplit_kernel<<<512, 256>>>(Wk, Wv);
    conv_mma_kernel<<<256, 512, CMM_SMEM>>>(conv_b, ln_in_g, ln_in_b);
    kv_mma_kernel<<<512, 512, CMM_SMEM>>>();

    for (int it = 0; it < 6; it++) {
        gemm_q_kernel<<<dim3(4, 8), 256, (16384+1024)*4>>>(Wq, ln_t_g, ln_t_b);
        attn_softmax_kernel<<<dim3(64, 8), 256>>>();
        gemm_c_kernel<<<dim3(4, 8, 8), 256>>>();
        finalize_kernel<<<8, 256, FIN_SMEM_FLOATS*4>>>(ln_m_g, ln_m_b);
        gemm_h_kernel<<<dim3(8, 8), 256, (16384+1024)*4>>>(W1, b1);
        gemm_o_kernel<<<dim3(4, 8), 256, GEMMO_SMEM_FLOATS*4>>>(W2, b2);
    }

    out_templates_kernel<<<8, 256>>>(out);
    out_attn_kernel<<<dim3(64, 8), 256>>>(out);
}

// round 9
// speedup vs baseline: 2.0083x; 1.0119x over previous
#include <cuda_runtime.h>
#include <cuda_bf16.h>
#include <stdint.h>
#include <math.h>

#define BATCH 8
#define DIM   256
#define NSLOT 64
#define LTOK  4096

typedef unsigned long long u64;

__device__ __forceinline__ u64 PK1(float v) {
    u64 r; asm("mov.b64 %0, {%1,%1};" : "=l"(r) : "f"(v)); return r;
}
__device__ __forceinline__ void FMA2(u64& d, u64 a, u64 b) {
    asm("fma.rn.f32x2 %0, %1, %2, %0;" : "+l"(d) : "l"(a), "l"(b));
}
__device__ __forceinline__ float2 UPK(u64 v) {
    float2 f; asm("mov.b64 {%0,%1}, %2;" : "=f"(f.x), "=f"(f.y) : "l"(v)); return f;
}

// ---------------- scratch ----------------
__device__ float g_templates[BATCH*NSLOT*DIM];
__device__ float g_tbuf[BATCH*NSLOT*DIM];
__device__ float g_attn[BATCH*LTOK*NSLOT];
__device__ float g_colsum_part[BATCH*64*NSLOT];
__device__ float g_colsum[BATCH*NSLOT];
__device__ float g_accpart[8*BATCH*NSLOT*DIM];
__device__ float g_hidden[BATCH*NSLOT*512];
// bf16 split operands
__device__ __nv_bfloat16 g_xh[36799488];
__device__ __nv_bfloat16 g_xl[36799488];
__device__ __nv_bfloat16 g_cwh[27*32768];
__device__ __nv_bfloat16 g_cwl[27*32768];
__device__ __nv_bfloat16 g_kvh[256*512];
__device__ __nv_bfloat16 g_kvl[256*512];
__device__ __nv_bfloat16 g_toksh[32768*256];
__device__ __nv_bfloat16 g_toksl[32768*256];
__device__ __nv_bfloat16 g_kh[32768*256];
__device__ __nv_bfloat16 g_kl[32768*256];
__device__ __nv_bfloat16 g_vh[32768*256];
__device__ __nv_bfloat16 g_vl[32768*256];
__device__ __nv_bfloat16 g_qh[BATCH*NSLOT*DIM];
__device__ __nv_bfloat16 g_ql[BATCH*NSLOT*DIM];
__device__ __nv_bfloat16 g_ath[BATCH*LTOK*NSLOT];
__device__ __nv_bfloat16 g_atl[BATCH*LTOK*NSLOT];

__device__ __forceinline__ float gelu_exact(float v) {
    return 0.5f * v * (1.0f + erff(v * 0.70710678118654752f));
}

// ========== mma.sync helpers ==========
__device__ __forceinline__ uint32_t smem_u32(const void* p) {
    uint32_t a;
    asm("{ .reg .u64 t; cvta.to.shared.u64 t, %1; cvt.u32.u64 %0, t; }" : "=r"(a) : "l"(p));
    return a;
}
__device__ __forceinline__ void ldsm_x4(uint32_t* r, uint32_t addr) {
    asm volatile("ldmatrix.sync.aligned.m8n8.x4.shared.b16 {%0,%1,%2,%3}, [%4];"
        : "=r"(r[0]), "=r"(r[1]), "=r"(r[2]), "=r"(r[3]) : "r"(addr));
}
__device__ __forceinline__ void ldsm_x4_t(uint32_t* r, uint32_t addr) {
    asm volatile("ldmatrix.sync.aligned.m8n8.x4.trans.shared.b16 {%0,%1,%2,%3}, [%4];"
        : "=r"(r[0]), "=r"(r[1]), "=r"(r[2]), "=r"(r[3]) : "r"(addr));
}
__device__ __forceinline__ void mma_bf16(float* d, const uint32_t* a, const uint32_t* b) {
    asm volatile("mma.sync.aligned.m16n8k16.row.col.f32.bf16.bf16.f32 "
        "{%0,%1,%2,%3}, {%4,%5,%6,%7}, {%8,%9}, {%0,%1,%2,%3};"
        : "+f"(d[0]), "+f"(d[1]), "+f"(d[2]), "+f"(d[3])
        : "r"(a[0]), "r"(a[1]), "r"(a[2]), "r"(a[3]), "r"(b[0]), "r"(b[1]));
}
__device__ __forceinline__ void bsplit(float v0, float v1, __nv_bfloat162& hh, __nv_bfloat162& ll) {
    __nv_bfloat16 h0 = __float2bfloat16(v0), h1 = __float2bfloat16(v1);
    hh.x = h0; hh.y = h1;
    ll.x = __float2bfloat16(v0 - __bfloat162float(h0));
    ll.y = __float2bfloat16(v1 - __bfloat162float(h1));
}

// 128x256 += A(128x128, pitch 272B) x B(128k x 256n, pitch 528B); 3-term bf16 split.
__device__ __forceinline__ void mma_chunk(
    uint32_t sAh, uint32_t sAl, uint32_t sBh, uint32_t sBl,
    float d[2][8][4], int wm, int wn, int lane)
{
    uint32_t aoff0 = (uint32_t)((wm*32 + (lane & 15))*272 + (lane >> 4)*16);
    uint32_t boff0 = (uint32_t)((lane & 15)*528 + (wn*64 + (lane >> 4)*8)*2);
    #pragma unroll
    for (int kk = 0; kk < 8; kk++) {
        uint32_t ah[8], al[8], bb[16];
        uint32_t ao = aoff0 + kk*32;
        ldsm_x4(ah,     sAh + ao);
        ldsm_x4(ah + 4, sAh + ao + 4352);
        ldsm_x4(al,     sAl + ao);
        ldsm_x4(al + 4, sAl + ao + 4352);
        uint32_t bo = boff0 + kk*8448;
        #pragma unroll
        for (int jj = 0; jj < 4; jj++) ldsm_x4_t(bb + jj*4, sBh + bo + jj*32);
        #pragma unroll
        for (int mi = 0; mi < 2; mi++) {
            #pragma unroll
            for (int j = 0; j < 8; j++) {
                const uint32_t* bf = bb + (j >> 1)*4 + (j & 1)*2;
                mma_bf16(d[mi][j], mi ? ah + 4 : ah, bf);
                mma_bf16(d[mi][j], mi ? al + 4 : al, bf);
            }
        }
        #pragma unroll
        for (int jj = 0; jj < 4; jj++) ldsm_x4_t(bb + jj*4, sBl + bo + jj*32);
        #pragma unroll
        for (int mi = 0; mi < 2; mi++) {
            #pragma unroll
            for (int j = 0; j < 8; j++) {
                const uint32_t* bf = bb + (j >> 1)*4 + (j & 1)*2;
                mma_bf16(d[mi][j], mi ? ah + 4 : ah, bf);
            }
        }
    }
}

// ---------------- prep kernels ----------------
__global__ void templates_init_kernel(const float* __restrict__ tinit) {
    int b = blockIdx.x, t = threadIdx.x;
    for (int n = 0; n < NSLOT; n++)
        g_templates[(b*NSLOT + n)*DIM + t] = tinit[n*DIM + t];
}

__global__ __launch_bounds__(256) void xsplit_kernel(const float* __restrict__ x) {
    __shared__ float st[128*33];
    int bid = blockIdx.x; int b = bid / 1089; int rem = bid % 1089; int d = rem / 33, h = rem % 33;
    int t = threadIdx.x, warp = t >> 5, lane = t & 31;
    const float* xb = x + ((((size_t)b*128)*33 + d)*33 + h)*33;
    for (int c = warp; c < 128; c += 8) {
        const float* src = xb + (size_t)c*35937;
        st[c*33 + lane] = src[lane];
        if (lane == 0) st[c*33 + 32] = src[32];
    }
    __syncthreads();
    size_t ob = ((((size_t)b*33 + d)*33 + h)*33)*128;
    for (int i = t; i < 33*128; i += 256) {
        int w = i >> 7, c = i & 127;
        float v = st[c*33 + w];
        __nv_bfloat16 hi = __float2bfloat16(v);
        g_xh[ob + (size_t)w*128 + c] = hi;
        g_xl[ob + (size_t)w*128 + c] = __float2bfloat16(v - __bfloat162float(hi));
    }
}

__global__ void cwsplit_kernel(const float* __restrict__ cw) {
    int idx = blockIdx.x*256 + threadIdx.x;
    int tap = idx >> 15, r = idx & 32767;
    int k = r >> 8, n = r & 255;
    float v = cw[(size_t)n*3456 + k*27 + tap];
    __nv_bfloat16 hi = __float2bfloat16(v);
    g_cwh[idx] = hi;
    g_cwl[idx] = __float2bfloat16(v - __bfloat162float(hi));
}

__global__ void kvsplit_kernel(const float* __restrict__ Wk, const float* __restrict__ Wv) {
    int idx = blockIdx.x*256 + threadIdx.x;
    int k = idx >> 9, c512 = idx & 511;
    int mat = c512 >> 8, col = c512 & 255;
    const float* W = mat ? Wv : Wk;
    float v = W[(size_t)k*256 + col];
    __nv_bfloat16 hi = __float2bfloat16(v);
    g_kvh[idx] = hi;
    g_kvl[idx] = __float2bfloat16(v - __bfloat162float(hi));
}

// ---------------- conv (implicit GEMM via mma.sync) + bias + ReLU + LN ----------------
#define CMM_SMEM 204800
__global__ __launch_bounds__(512, 1) void conv_mma_kernel(
    const float* __restrict__ convb, const float* __restrict__ lng, const float* __restrict__ lnb)
{
    extern __shared__ char sm[];
    uint32_t sb = smem_u32(sm);
    const uint32_t oAh = 0, oAl = 34816, oBh = 69632, oBl = 137216;
    int t = threadIdx.x, lane = t & 31, wid = t >> 5;
    int wm = wid >> 2, wn = wid & 3;
    int bx = blockIdx.x; int b = bx >> 5, xd = (bx >> 1) & 15, half = bx & 1;

    float d[2][8][4];
    #pragma unroll
    for (int i = 0; i < 2; i++)
        #pragma unroll
        for (int j = 0; j < 8; j++)
            #pragma unroll
            for (int c = 0; c < 4; c++) d[i][j][c] = 0.f;

    int m = t >> 2, q = t & 3;
    int xhl = m >> 4, xw = m & 15;

    for (int tap = 0; tap < 27; tap++) {
        int kd = tap/9, r9 = tap%9, kh = r9/3, kw = r9%3;
        {
            size_t xi = ((((size_t)(b*33) + 2*xd + kd)*33 + 2*(half*8 + xhl) + kh)*33 + 2*xw + kw)*128 + q*32;
            const uint4* shi = (const uint4*)(g_xh + xi);
            const uint4* slo = (const uint4*)(g_xl + xi);
            char* dh = sm + oAh + m*272 + q*64;
            char* dl = sm + oAl + m*272 + q*64;
            #pragma unroll
            for (int j = 0; j < 4; j++) {
                *(uint4*)(dh + j*16) = shi[j];
                *(uint4*)(dl + j*16) = slo[j];
            }
        }
        {
            const uint4* s1 = (const uint4*)(g_cwh + tap*32768);
            const uint4* s2 = (const uint4*)(g_cwl + tap*32768);
            #pragma unroll
            for (int it = 0; it < 8; it++) {
                int i = t + it*512;
                int row = i >> 5, seg = i & 31;
                *(uint4*)(sm + oBh + row*528 + seg*16) = s1[i];
                *(uint4*)(sm + oBl + row*528 + seg*16) = s2[i];
            }
        }
        __syncthreads();
        mma_chunk(sb + oAh, sb + oAl, sb + oBh, sb + oBl, d, wm, wn, lane);
        __syncthreads();
    }

    float* stg = (float*)sm;
    {
        int r0 = wm*32 + (lane >> 2);
        int c0 = wn*64 + (lane & 3)*2;
        #pragma unroll
        for (int mi = 0; mi < 2; mi++)
            #pragma unroll
            for (int j = 0; j < 8; j++) {
                int rr = r0 + mi*16, cc = c0 + j*8;
                *(float2*)(stg + (size_t)rr*264 + cc)     = make_float2(d[mi][j][0], d[mi][j][1]);
                *(float2*)(stg + (size_t)(rr+8)*264 + cc) = make_float2(d[mi][j][2], d[mi][j][3]);
            }
    }
    __syncthreads();

    {
        int tok = t >> 2, q2 = t & 3;
        const float* src = stg + (size_t)tok*264 + q2*64;
        float z[64];
        float s = 0.f, sq = 0.f;
        #pragma unroll
        for (int i = 0; i < 64; i++) {
            float v = fmaxf(src[i] + convb[q2*64 + i], 0.f);
            z[i] = v; s += v; sq += v*v;
        }
        s  += __shfl_xor_sync(0xffffffffu, s, 1);  s  += __shfl_xor_sync(0xffffffffu, s, 2);
        sq += __shfl_xor_sync(0xffffffffu, sq, 1); sq += __shfl_xor_sync(0xffffffffu, sq, 2);
        float mu = s * (1.f/256.f);
        float rs = rsqrtf(sq * (1.f/256.f) - mu*mu + 1e-5f);
        int l = (xd*16 + half*8 + (tok >> 4))*16 + (tok & 15);
        size_t tg = ((size_t)b*4096 + l)*256 + q2*64;
        #pragma unroll
        for (int i = 0; i < 64; i += 2) {
            int ch = q2*64 + i;
            float v0 = (z[i]   - mu)*rs*lng[ch]   + lnb[ch];
            float v1 = (z[i+1] - mu)*rs*lng[ch+1] + lnb[ch+1];
            __nv_bfloat162 hh, ll;
            bsplit(v0, v1, hh, ll);
            *(__nv_bfloat162*)(g_toksh + tg + i) = hh;
            *(__nv_bfloat162*)(g_toksl + tg + i) = ll;
        }
    }
}

// ---------------- K/V projection via mma.sync -> bf16 split outputs ----------------
__global__ __launch_bounds__(512, 1) void kv_mma_kernel() {
    extern __shared__ char sm[];
    uint32_t sb = smem_u32(sm);
    const uint32_t oAh = 0, oAl = 34816, oBh = 69632, oBl = 137216;
    int t = threadIdx.x, lane = t & 31, wid = t >> 5;
    int wm = wid >> 2, wn = wid & 3;
    int nhalf = blockIdx.x & 1, chunk = blockIdx.x >> 1;

    float d[2][8][4];
    #pragma unroll
    for (int i = 0; i < 2; i++)
        #pragma unroll
        for (int j = 0; j < 8; j++)
            #pragma unroll
            for (int c = 0; c < 4; c++) d[i][j][c] = 0.f;

    int m = t >> 2, q = t & 3;
    for (int kc = 0; kc < 2; kc++) {
        {
            size_t ti = ((size_t)(chunk*128 + m))*256 + kc*128 + q*32;
            const uint4* shi = (const uint4*)(g_toksh + ti);
            const uint4* slo = (const uint4*)(g_toksl + ti);
            char* dh = sm + oAh + m*272 + q*64;
            char* dl = sm + oAl + m*272 + q*64;
            #pragma unroll
            for (int j = 0; j < 4; j++) {
                *(uint4*)(dh + j*16) = shi[j];
                *(uint4*)(dl + j*16) = slo[j];
            }
        }
        {
            #pragma unroll
            for (int it = 0; it < 8; it++) {
                int i = t + it*512;
                int row = i >> 5, seg = i & 31;
                size_t off = (size_t)(kc*128 + row)*512 + nhalf*256 + seg*8;
                *(uint4*)(sm + oBh + row*528 + seg*16) = *(const uint4*)(g_kvh + off);
                *(uint4*)(sm + oBl + row*528 + seg*16) = *(const uint4*)(g_kvl + off);
            }
        }
        __syncthreads();
        mma_chunk(sb + oAh, sb + oAl, sb + oBh, sb + oBl, d, wm, wn, lane);
        __syncthreads();
    }

    __nv_bfloat16* dh = nhalf ? g_vh : g_kh;
    __nv_bfloat16* dl = nhalf ? g_vl : g_kl;
    int r0 = wm*32 + (lane >> 2);
    int c0 = wn*64 + (lane & 3)*2;
    #pragma unroll
    for (int mi = 0; mi < 2; mi++)
        #pragma unroll
        for (int j = 0; j < 8; j++) {
            int rr = r0 + mi*16, cc = c0 + j*8;
            size_t tok = (size_t)chunk*128 + rr;
            __nv_bfloat162 hh, ll;
            bsplit(d[mi][j][0], d[mi][j][1], hh, ll);
            *(__nv_bfloat162*)(dh + tok*256 + cc) = hh;
            *(__nv_bfloat162*)(dl + tok*256 + cc) = ll;
            bsplit(d[mi][j][2], d[mi][j][3], hh, ll);
            *(__nv_bfloat162*)(dh + (tok+8)*256 + cc) = hh;
            *(__nv_bfloat162*)(dl + (tok+8)*256 + cc) = ll;
        }
}

// ---------------- fused LN_t + q-GEMM (scalar, proven) -> bf16 split q ----------------
__global__ __launch_bounds__(256) void gemm_q_kernel(
    const float* __restrict__ Wq, const float* __restrict__ lng, const float* __restrict__ lnb)
{
    extern __shared__ float smf[];
    float* Af = smf; float* Bs = smf + 16384;
    int b = blockIdx.y; int nc = blockIdx.x * 64;
    int t = threadIdx.x;
    {
        int r = t >> 2, part = t & 3;
        const float* row = g_templates + ((size_t)(b*NSLOT) + r)*DIM + part*64;
        float s = 0.f, sq = 0.f;
        #pragma unroll
        for (int i = 0; i < 64; i += 4) {
            float4 v = *(const float4*)(row + i);
            s += v.x+v.y+v.z+v.w;
            sq += v.x*v.x + v.y*v.y + v.z*v.z + v.w*v.w;
        }
        s  += __shfl_xor_sync(0xffffffffu, s, 1);  s  += __shfl_xor_sync(0xffffffffu, s, 2);
        sq += __shfl_xor_sync(0xffffffffu, sq, 1); sq += __shfl_xor_sync(0xffffffffu, sq, 2);
        float mu = s * (1.0f/256.0f);
        float rs = rsqrtf(sq * (1.0f/256.0f) - mu*mu + 1e-5f);
        #pragma unroll
        for (int i = 0; i < 64; i += 4) {
            float4 v = *(const float4*)(row + i);
            float4 gg = *(const float4*)(lng + part*64 + i);
            float4 bv = *(const float4*)(lnb + part*64 + i);
            Af[(part*64+i+0)*64 + r] = (v.x - mu)*rs*gg.x + bv.x;
            Af[(part*64+i+1)*64 + r] = (v.y - mu)*rs*gg.y + bv.y;
            Af[(part*64+i+2)*64 + r] = (v.z - mu)*rs*gg.z + bv.z;
            Af[(part*64+i+3)*64 + r] = (v.w - mu)*rs*gg.w + bv.w;
        }
    }
    __syncthreads();
    int tm = t >> 4, tn = t & 15;
    u64 acc[4][2] = {};
    int kk0 = t >> 4, n4 = (t & 15)*4;
    for (int k0 = 0; k0 < 256; k0 += 16) {
        *(float4*)(Bs + kk0*64 + n4) = *(const float4*)(Wq + (size_t)(k0+kk0)*256 + nc + n4);
        __syncthreads();
        #pragma unroll
        for (int kk = 0; kk < 16; kk++) {
            ulonglong2 a2 = *(ulonglong2*)(Af + (k0+kk)*64 + tm*4);
            float4 bb = *(float4*)(Bs + kk*64 + tn*4);
            u64 q0 = PK1(bb.x), q1 = PK1(bb.y), q2 = PK1(bb.z), q3 = PK1(bb.w);
            FMA2(acc[0][0], a2.x, q0); FMA2(acc[0][1], a2.y, q0);
            FMA2(acc[1][0], a2.x, q1); FMA2(acc[1][1], a2.y, q1);
            FMA2(acc[2][0], a2.x, q2); FMA2(acc[2][1], a2.y, q2);
            FMA2(acc[3][0], a2.x, q3); FMA2(acc[3][1], a2.y, q3);
        }
        __syncthreads();
    }
    const float scale = 0.0625f;
    #pragma unroll
    for (int p = 0; p < 2; p++) {
        float2 f0 = UPK(acc[0][p]), f1 = UPK(acc[1][p]), f2 = UPK(acc[2][p]), f3 = UPK(acc[3][p]);
        int mm = tm*4 + p*2;
        size_t o0 = ((size_t)(b*NSLOT) + mm)*DIM + nc + tn*4;
        __nv_bfloat162 hh, ll;
        bsplit(f0.x*scale, f1.x*scale, hh, ll);
        *(__nv_bfloat162*)(g_qh + o0) = hh; *(__nv_bfloat162*)(g_ql + o0) = ll;
        bsplit(f2.x*scale, f3.x*scale, hh, ll);
        *(__nv_bfloat162*)(g_qh + o0 + 2) = hh; *(__nv_bfloat162*)(g_ql + o0 + 2) = ll;
        bsplit(f0.y*scale, f1.y*scale, hh, ll);
        *(__nv_bfloat162*)(g_qh + o0 + DIM) = hh; *(__nv_bfloat162*)(g_ql + o0 + DIM) = ll;
        bsplit(f2.y*scale, f3.y*scale, hh, ll);
        *(__nv_bfloat162*)(g_qh + o0 + DIM + 2) = hh; *(__nv_bfloat162*)(g_ql + o0 + DIM + 2) = ll;
    }
}

// ---------------- attn logits via mma + softmax + colsum partials ----------------
// grid (32, 8), block 256. smem: Ah 0(34816), Al 34816, Qh 69632(17408), Ql 87040. total 104448.
#define ATT_SMEM 104448
__global__ __launch_bounds__(256) void attn_mma_kernel() {
    extern __shared__ char sm[];
    uint32_t sb = smem_u32(sm);
    const uint32_t oAh = 0, oAl = 34816, oQh = 69632, oQl = 87040;
    int t = threadIdx.x, lane = t & 31, wid = t >> 5;
    int wm = wid >> 1, wn = wid & 1;   // wm: 4 l-tiles of 32; wn: 2 slot-tiles of 32
    int lb = blockIdx.x, b = blockIdx.y;

    float d[2][4][4];
    #pragma unroll
    for (int i = 0; i < 2; i++)
        #pragma unroll
        for (int j = 0; j < 4; j++)
            #pragma unroll
            for (int c = 0; c < 4; c++) d[i][j][c] = 0.f;

    for (int kc = 0; kc < 2; kc++) {
        {   // A: 128 l-rows x 128 k
            int row = t >> 1, half = t & 1;
            size_t ti = ((size_t)(b*4096) + lb*128 + row)*256 + kc*128 + half*64;
            const uint4* shi = (const uint4*)(g_kh + ti);
            const uint4* slo = (const uint4*)(g_kl + ti);
            char* dh = sm + oAh + row*272 + half*128;
            char* dl = sm + oAl + row*272 + half*128;
            #pragma unroll
            for (int j = 0; j < 8; j++) {
                *(uint4*)(dh + j*16) = shi[j];
                *(uint4*)(dl + j*16) = slo[j];
            }
        }
        {   // Q: 64 slot-rows x 128 k
            int row = t >> 2, q4 = t & 3;
            size_t ti = ((size_t)(b*NSLOT) + row)*256 + kc*128 + q4*32;
            const uint4* shi = (const uint4*)(g_qh + ti);
            const uint4* slo = (const uint4*)(g_ql + ti);
            char* dh = sm + oQh + row*272 + q4*64;
            char* dl = sm + oQl + row*272 + q4*64;
            #pragma unroll
            for (int j = 0; j < 4; j++) {
                *(uint4*)(dh + j*16) = shi[j];
                *(uint4*)(dl + j*16) = slo[j];
            }
        }
        __syncthreads();
        uint32_t aoff0 = (uint32_t)((wm*32 + (lane & 15))*272 + (lane >> 4)*16);
        uint32_t qoff0 = (uint32_t)(((lane >> 4)*8 + (lane & 7) + wn*32)*272 + ((lane >> 3) & 1)*16);
        #pragma unroll
        for (int kk = 0; kk < 8; kk++) {
            uint32_t ah[8], al[8], qh8[8], ql8[8];
            uint32_t ao = aoff0 + kk*32;
            ldsm_x4(ah,     sb + oAh + ao);
            ldsm_x4(ah + 4, sb + oAh + ao + 16*272);
            ldsm_x4(al,     sb + oAl + ao);
            ldsm_x4(al + 4, sb + oAl + ao + 16*272);
            uint32_t qo = qoff0 + kk*32;
            ldsm_x4(qh8,     sb + oQh + qo);
            ldsm_x4(qh8 + 4, sb + oQh + qo + 16*272);
            ldsm_x4(ql8,     sb + oQl + qo);
            ldsm_x4(ql8 + 4, sb + oQl + qo + 16*272);
            #pragma unroll
            for (int mi = 0; mi < 2; mi++) {
                #pragma unroll
                for (int j = 0; j < 4; j++) {
                    const uint32_t* bh = qh8 + (j >> 1)*4 + (j & 1)*2;
                    const uint32_t* bl = ql8 + (j >> 1)*4 + (j & 1)*2;
                    const uint32_t* am = mi ? ah + 4 : ah;
                    const uint32_t* aml = mi ? al + 4 : al;
                    mma_bf16(d[mi][j], am, bh);
                    mma_bf16(d[mi][j], am, bl);
                    mma_bf16(d[mi][j], aml, bh);
                }
            }
        }
        __syncthreads();
    }

    // stage logits fp32 [128][68]
    float* stg = (float*)sm;
    {
        int r0 = wm*32 + (lane >> 2);
        int c0 = wn*32 + (lane & 3)*2;
        #pragma unroll
        for (int mi = 0; mi < 2; mi++)
            #pragma unroll
            for (int j = 0; j < 4; j++) {
                int rr = r0 + mi*16, cc = c0 + j*8;
                *(float2*)(stg + rr*68 + cc)     = make_float2(d[mi][j][0], d[mi][j][1]);
                *(float2*)(stg + (rr+8)*68 + cc) = make_float2(d[mi][j][2], d[mi][j][3]);
            }
    }
    __syncthreads();

    // softmax per row (2 threads/row)
    {
        int row = t >> 1, half = t & 1;
        float* sr = stg + row*68 + half*32;
        float a[32];
        float mx = -3.4e38f;
        #pragma unroll
        for (int i = 0; i < 32; i++) { a[i] = sr[i]; mx = fmaxf(mx, a[i]); }
        mx = fmaxf(mx, __shfl_xor_sync(0xffffffffu, mx, 1));
        float s = 0.f;
        #pragma unroll
        for (int i = 0; i < 32; i++) { a[i] = expf(a[i] - mx); s += a[i]; }
        s += __shfl_xor_sync(0xffffffffu, s, 1);
        float inv = 1.0f / s;
        size_t gi = ((size_t)(b*4096) + lb*128 + row)*64 + half*32;
        #pragma unroll
        for (int i = 0; i < 32; i++) { a[i] = a[i]*inv + 1e-8f; sr[i] = a[i]; }
        #pragma unroll
        for (int i = 0; i < 32; i += 4)
            *(float4*)(g_attn + gi + i) = make_float4(a[i], a[i+1], a[i+2], a[i+3]);
        #pragma unroll
        for (int i = 0; i < 32; i += 2) {
            __nv_bfloat162 hh, ll;
            bsplit(a[i], a[i+1], hh, ll);
            *(__nv_bfloat162*)(g_ath + gi + i) = hh;
            *(__nv_bfloat162*)(g_atl + gi + i) = ll;
        }
    }
    __syncthreads();
    if (t < 64) {
        float s = 0.f;
        for (int r = 0; r < 128; r++) s += stg[r*68 + t];
        g_colsum_part[((size_t)b*64 + lb)*NSLOT + t] = s;
    }
}

// ---------------- attn^T @ v via mma. grid (2 dhalf, 8 psplit, 8 b), block 256 ----------------
// smem: Ath 0(18432: 128x144), Atl 18432, Vh 36864(34816), Vl 71680. total 106496.
#define GC_SMEM 106496
__global__ __launch_bounds__(256) void gemm_c_mma_kernel() {
    extern __shared__ char sm[];
    uint32_t sb = smem_u32(sm);
    const uint32_t oAth = 0, oAtl = 18432, oVh = 36864, oVl = 71680;
    int t = threadIdx.x, lane = t & 31, wid = t >> 5;
    int wm = wid & 1, wn = wid >> 1;   // wm: 2 slot-tiles of 32; wn: 4 d-tiles of 32
    int dh = blockIdx.x, ps = blockIdx.y, b = blockIdx.z;

    float d[2][4][4];
    #pragma unroll
    for (int i = 0; i < 2; i++)
        #pragma unroll
        for (int j = 0; j < 4; j++)
            #pragma unroll
            for (int c = 0; c < 4; c++) d[i][j][c] = 0.f;

    for (int lc = 0; lc < 4; lc++) {
        int l0 = ps*512 + lc*128;
        {   // At: 128 l x 64 n, pitch 144
            int row = t >> 1, half = t & 1;
            size_t ti = ((size_t)(b*4096) + l0 + row)*64 + half*32;
            const uint4* shi = (const uint4*)(g_ath + ti);
            const uint4* slo = (const uint4*)(g_atl + ti);
            char* dst_h = sm + oAth + row*144 + half*64;
            char* dst_l = sm + oAtl + row*144 + half*64;
            #pragma unroll
            for (int j = 0; j < 4; j++) {
                *(uint4*)(dst_h + j*16) = shi[j];
                *(uint4*)(dst_l + j*16) = slo[j];
            }
        }
        {   // Vt: 128 l x 128 d, pitch 272
            int row = t >> 1, half = t & 1;
            size_t ti = ((size_t)(b*4096) + l0 + row)*256 + dh*128 + half*64;
            const uint4* shi = (const uint4*)(g_vh + ti);
            const uint4* slo = (const uint4*)(g_vl + ti);
            char* dst_h = sm + oVh + row*272 + half*128;
            char* dst_l = sm + oVl + row*272 + half*128;
            #pragma unroll
            for (int j = 0; j < 8; j++) {
                *(uint4*)(dst_h + j*16) = shi[j];
                *(uint4*)(dst_l + j*16) = slo[j];
            }
        }
        __syncthreads();
        uint32_t aoff0 = (uint32_t)((((lane >> 4)*8 + (lane & 7)))*144 + ((lane >> 3) & 1)*16 + wm*64);
        uint32_t boff0 = (uint32_t)((lane & 15)*272 + (wn*32 + (lane >> 4)*8)*2);
        #pragma unroll
        for (int kk = 0; kk < 8; kk++) {
            uint32_t ah[8], al[8], bh8[8], bl8[8];
            uint32_t ao = aoff0 + kk*16*144;
            ldsm_x4_t(ah,     sb + oAth + ao);
            ldsm_x4_t(ah + 4, sb + oAth + ao + 32);
            ldsm_x4_t(al,     sb + oAtl + ao);
            ldsm_x4_t(al + 4, sb + oAtl + ao + 32);
            uint32_t bo = boff0 + kk*16*272;
            ldsm_x4_t(bh8,     sb + oVh + bo);
            ldsm_x4_t(bh8 + 4, sb + oVh + bo + 32);
            ldsm_x4_t(bl8,     sb + oVl + bo);
            ldsm_x4_t(bl8 + 4, sb + oVl + bo + 32);
            #pragma unroll
            for (int mi = 0; mi < 2; mi++) {
                #pragma unroll
                for (int j = 0; j < 4; j++) {
                    const uint32_t* bfh = bh8 + (j >> 1)*4 + (j & 1)*2;
                    const uint32_t* bfl = bl8 + (j >> 1)*4 + (j & 1)*2;
                    const uint32_t* am = mi ? ah + 4 : ah;
                    const uint32_t* aml = mi ? al + 4 : al;
                    mma_bf16(d[mi][j], am, bfh);
                    mma_bf16(d[mi][j], am, bfl);
                    mma_bf16(d[mi][j], aml, bfh);
                }
            }
        }
        __syncthreads();
    }

    int r0 = wm*32 + (lane >> 2);
    int c0 = dh*128 + wn*32 + (lane & 3)*2;
    float* C = g_accpart + ((size_t)((ps*BATCH + b)*NSLOT))*DIM;
    #pragma unroll
    for (int mi = 0; mi < 2; mi++)
        #pragma unroll
        for (int j = 0; j < 4; j++) {
            int slot = r0 + mi*16, cc = c0 + j*8;
            *(float2*)(C + (size_t)slot*DIM + cc)     = make_float2(d[mi][j][0], d[mi][j][1]);
            *(float2*)(C + (size_t)(slot+8)*DIM + cc) = make_float2(d[mi][j][2], d[mi][j][3]);
        }
}

// ---------------- MLP kernels (scalar, proven) ----------------
__global__ __launch_bounds__(256) void gemm_h_kernel(const float* __restrict__ W1,
                                                     const float* __restrict__ b1)
{
    extern __shared__ float smf[];
    float* Af = smf; float* Bs = smf + 16384;
    int b = blockIdx.y; int nc = blockIdx.x * 64;
    int t = threadIdx.x;
    {
        int r = t >> 2, part = t & 3;
        const float* row = g_tbuf + ((size_t)(b*NSLOT) + r)*DIM + part*64;
        #pragma unroll
        for (int i = 0; i < 64; i += 4) {
            float4 v = *(const float4*)(row + i);
            Af[(part*64+i+0)*64 + r] = v.x;
            Af[(part*64+i+1)*64 + r] = v.y;
            Af[(part*64+i+2)*64 + r] = v.z;
            Af[(part*64+i+3)*64 + r] = v.w;
        }
    }
    __syncthreads();
    int tm = t >> 4, tn = t & 15;
    u64 acc[4][2] = {};
    int kk0 = t >> 4, n4 = (t & 15)*4;
    for (int k0 = 0; k0 < 256; k0 += 16) {
        *(float4*)(Bs + kk0*64 + n4) = *(const float4*)(W1 + (size_t)(k0+kk0)*512 + nc + n4);
        __syncthreads();
        #pragma unroll
        for (int kk = 0; kk < 16; kk++) {
            ulonglong2 a2 = *(ulonglong2*)(Af + (k0+kk)*64 + tm*4);
            float4 bb = *(float4*)(Bs + kk*64 + tn*4);
            u64 q0 = PK1(bb.x), q1 = PK1(bb.y), q2 = PK1(bb.z), q3 = PK1(bb.w);
            FMA2(acc[0][0], a2.x, q0); FMA2(acc[0][1], a2.y, q0);
            FMA2(acc[1][0], a2.x, q1); FMA2(acc[1][1], a2.y, q1);
            FMA2(acc[2][0], a2.x, q2); FMA2(acc[2][1], a2.y, q2);
            FMA2(acc[3][0], a2.x, q3); FMA2(acc[3][1], a2.y, q3);
        }
        __syncthreads();
    }
    float4 bv = *(const float4*)(b1 + nc + tn*4);
    #pragma unroll
    for (int p = 0; p < 2; p++) {
        float2 f0 = UPK(acc[0][p]), f1 = UPK(acc[1][p]), f2 = UPK(acc[2][p]), f3 = UPK(acc[3][p]);
        float4 r0 = {gelu_exact(f0.x+bv.x), gelu_exact(f1.x+bv.y), gelu_exact(f2.x+bv.z), gelu_exact(f3.x+bv.w)};
        float4 r1 = {gelu_exact(f0.y+bv.x), gelu_exact(f1.y+bv.y), gelu_exact(f2.y+bv.z), gelu_exact(f3.y+bv.w)};
        int mm = tm*4 + p*2;
        *(float4*)(g_hidden + ((size_t)(b*NSLOT) + mm  )*512 + nc + tn*4) = r0;
        *(float4*)(g_hidden + ((size_t)(b*NSLOT) + mm+1)*512 + nc + tn*4) = r1;
    }
}

#define GEMMO_SMEM_FLOATS (32768 + 1024)
__global__ __launch_bounds__(256) void gemm_o_kernel(const float* __restrict__ W2,
                                                     const float* __restrict__ b2)
{
    extern __shared__ float smf[];
    float* Af = smf; float* Bs = smf + 32768;
    int b = blockIdx.y; int nc = blockIdx.x * 64;
    int t = threadIdx.x;
    {
        int r = t >> 2, part = t & 3;
        const float* row = g_hidden + ((size_t)(b*NSLOT) + r)*512 + part*128;
        #pragma unroll
        for (int i = 0; i < 128; i += 4) {
            float4 v = *(const float4*)(row + i);
            Af[(part*128+i+0)*64 + r] = v.x;
            Af[(part*128+i+1)*64 + r] = v.y;
            Af[(part*128+i+2)*64 + r] = v.z;
            Af[(part*128+i+3)*64 + r] = v.w;
        }
    }
    __syncthreads();
    int tm = t >> 4, tn = t & 15;
    u64 acc[4][2] = {};
    int kk0 = t >> 4, n4 = (t & 15)*4;
    for (int k0 = 0; k0 < 512; k0 += 16) {
        *(float4*)(Bs + kk0*64 + n4) = *(const float4*)(W2 + (size_t)(k0+kk0)*256 + nc + n4);
        __syncthreads();
        #pragma unroll
        for (int kk = 0; kk < 16; kk++) {
            ulonglong2 a2 = *(ulonglong2*)(Af + (k0+kk)*64 + tm*4);
            float4 bb = *(float4*)(Bs + kk*64 + tn*4);
            u64 q0 = PK1(bb.x), q1 = PK1(bb.y), q2 = PK1(bb.z), q3 = PK1(bb.w);
            FMA2(acc[0][0], a2.x, q0); FMA2(acc[0][1], a2.y, q0);
            FMA2(acc[1][0], a2.x, q1); FMA2(acc[1][1], a2.y, q1);
            FMA2(acc[2][0], a2.x, q2); FMA2(acc[2][1], a2.y, q2);
            FMA2(acc[3][0], a2.x, q3); FMA2(acc[3][1], a2.y, q3);
        }
        __syncthreads();
    }
    float4 bv = *(const float4*)(b2 + nc + tn*4);
    #pragma unroll
    for (int p = 0; p < 2; p++) {
        float2 f0 = UPK(acc[0][p]), f1 = UPK(acc[1][p]), f2 = UPK(acc[2][p]), f3 = UPK(acc[3][p]);
        int mm = tm*4 + p*2;
        float* C0 = g_templates + ((size_t)(b*NSLOT) + mm)*DIM + nc + tn*4;
        float4 c0 = *(float4*)C0;
        c0.x += f0.x + bv.x; c0.y += f1.x + bv.y; c0.z += f2.x + bv.z; c0.w += f3.x + bv.w;
        *(float4*)C0 = c0;
        float* C1 = C0 + DIM;
        float4 c1 = *(float4*)C1;
        c1.x += f0.y + bv.x; c1.y += f1.y + bv.y; c1.z += f2.y + bv.z; c1.w += f3.y + bv.w;
        *(float4*)C1 = c1;
    }
}

// ---------------- fused colsum + template update + LN_m. grid 8 ----------------
#define FIN_SMEM_FLOATS (16384 + 256 + 64)
__global__ __launch_bounds__(256) void finalize_kernel(const float* __restrict__ g,
                                                       const float* __restrict__ bb) {
    extern __shared__ float smf[];
    float* tv   = smf;
    float* csp  = smf + 16384;
    float* csin = smf + 16640;
    int b = blockIdx.x, t = threadIdx.x;
    {
        int part4 = t >> 6, n = t & 63;
        float s = 0.f;
        #pragma unroll
        for (int lb = 0; lb < 8; lb++)
            s += g_colsum_part[((size_t)b*64 + part4*8 + lb)*NSLOT + n];
        csp[part4*64 + n] = s;
    }
    __syncthreads();
    if (t < 64) {
        float tot = csp[t] + csp[64+t] + csp[128+t] + csp[192+t];
        g_colsum[b*NSLOT + t] = tot;
        csin[t] = 1.0f / tot;
    }
    __syncthreads();
    for (int n = 0; n < NSLOT; n++) {
        float s = 0.f;
        #pragma unroll
        for (int p = 0; p < 8; p++)
            s += g_accpart[((size_t)((p*BATCH + b)*NSLOT) + n)*DIM + t];
        size_t idx = ((size_t)(b*NSLOT) + n)*DIM + t;
        float val = g_templates[idx] + s * csin[n];
        g_templates[idx] = val;
        tv[n*256 + t] = val;
    }
    __syncthreads();
    {
        int r = t >> 2, part = t & 3;
        const float* row = tv + r*256 + part*64;
        float s = 0.f, sq = 0.f;
        #pragma unroll
        for (int i = 0; i < 64; i += 4) {
            float4 v = *(const float4*)(row + i);
            s += v.x+v.y+v.z+v.w;
            sq += v.x*v.x + v.y*v.y + v.z*v.z + v.w*v.w;
        }
        s  += __shfl_xor_sync(0xffffffffu, s, 1);  s  += __shfl_xor_sync(0xffffffffu, s, 2);
        sq += __shfl_xor_sync(0xffffffffu, sq, 1); sq += __shfl_xor_sync(0xffffffffu, sq, 2);
        float mu = s * (1.0f/256.0f);
        float rs = rsqrtf(sq * (1.0f/256.0f) - mu*mu + 1e-5f);
        float* drow = g_tbuf + ((size_t)(b*NSLOT) + r)*DIM + part*64;
        #pragma unroll
        for (int i = 0; i < 64; i += 4) {
            float4 v = *(const float4*)(row + i);
            float4 gg = *(const float4*)(g + part*64 + i);
            float4 bv = *(const float4*)(bb + part*64 + i);
            float4 o;
            o.x = (v.x - mu)*rs*gg.x + bv.x;
            o.y = (v.y - mu)*rs*gg.y + bv.y;
            o.z = (v.z - mu)*rs*gg.z + bv.z;
            o.w = (v.w - mu)*rs*gg.w + bv.w;
            *(float4*)(drow + i) = o;
        }
    }
}

// ---------------- outputs ----------------
__global__ void out_templates_kernel(float* __restrict__ out) {
    int b = blockIdx.x, d = threadIdx.x;
    for (int n = 0; n < NSLOT; n++)
        out[((size_t)(b*DIM) + d)*NSLOT + n] = g_templates[((size_t)(b*NSLOT) + n)*DIM + d];
}

__global__ void out_attn_kernel(float* __restrict__ out) {
    int n = blockIdx.x, b = blockIdx.y, t = threadIdx.x;
    float inv = 1.0f / g_colsum[b*NSLOT + n];
    size_t base = (size_t)BATCH*DIM*NSLOT + ((size_t)(b*NSLOT + n))*LTOK;
    for (int k = 0; k < 16; k++) {
        int l = k*256 + t;
        out[base + l] = g_attn[((size_t)b*LTOK + l)*NSLOT + n] * inv;
    }
}

// ---------------- launch ----------------
extern "C" void kernel_launch(void* const* d_in, const int* in_sizes, int n_in,
                              void* d_out, int out_size) {
    const float* x       = (const float*)d_in[0];
    const float* tinit   = (const float*)d_in[1];
    const float* conv_w  = (const float*)d_in[2];
    const float* conv_b  = (const float*)d_in[3];
    const float* Wq      = (const float*)d_in[4];
    const float* Wk      = (const float*)d_in[5];
    const float* Wv      = (const float*)d_in[6];
    const float* ln_in_g = (const float*)d_in[7];
    const float* ln_in_b = (const float*)d_in[8];
    const float* ln_t_g  = (const float*)d_in[9];
    const float* ln_t_b  = (const float*)d_in[10];
    const float* ln_m_g  = (const float*)d_in[11];
    const float* ln_m_b  = (const float*)d_in[12];
    const float* W1      = (const float*)d_in[13];
    const float* b1      = (const float*)d_in[14];
    const float* W2      = (const float*)d_in[15];
    const float* b2      = (const float*)d_in[16];
    float* out = (float*)d_out;

    cudaFuncSetAttribute(conv_mma_kernel, cudaFuncAttributeMaxDynamicSharedMemorySize, CMM_SMEM);
    cudaFuncSetAttribute(kv_mma_kernel, cudaFuncAttributeMaxDynamicSharedMemorySize, CMM_SMEM);
    cudaFuncSetAttribute(attn_mma_kernel, cudaFuncAttributeMaxDynamicSharedMemorySize, ATT_SMEM);
    cudaFuncSetAttribute(gemm_c_mma_kernel, cudaFuncAttributeMaxDynamicSharedMemorySize, GC_SMEM);
    cudaFuncSetAttribute(gemm_q_kernel, cudaFuncAttributeMaxDynamicSharedMemorySize, (16384+1024)*4);
    cudaFuncSetAttribute(gemm_h_kernel, cudaFuncAttributeMaxDynamicSharedMemorySize, (16384+1024)*4);
    cudaFuncSetAttribute(gemm_o_kernel, cudaFuncAttributeMaxDynamicSharedMemorySize, GEMMO_SMEM_FLOATS*4);
    cudaFuncSetAttribute(finalize_kernel, cudaFuncAttributeMaxDynamicSharedMemorySize, FIN_SMEM_FLOATS*4);

    templates_init_kernel<<<8, 256>>>(tinit);
    xsplit_kernel<<<8*33*33, 256>>>(x);
    cwsplit_kernel<<<3456, 256>>>(conv_w);
    kvsplit_kernel<<<512, 256>>>(Wk, Wv);
    conv_mma_kernel<<<256, 512, CMM_SMEM>>>(conv_b, ln_in_g, ln_in_b);
    kv_mma_kernel<<<512, 512, CMM_SMEM>>>();

    for (int it = 0; it < 6; it++) {
        gemm_q_kernel<<<dim3(4, 8), 256, (16384+1024)*4>>>(Wq, ln_t_g, ln_t_b);
        attn_mma_kernel<<<dim3(32, 8), 256, ATT_SMEM>>>();
        gemm_c_mma_kernel<<<dim3(2, 8, 8), 256, GC_SMEM>>>();
        finalize_kernel<<<8, 256, FIN_SMEM_FLOATS*4>>>(ln_m_g, ln_m_b);
        gemm_h_kernel<<<dim3(8, 8), 256, (16384+1024)*4>>>(W1, b1);
        gemm_o_kernel<<<dim3(4, 8), 256, GEMMO_SMEM_FLOATS*4>>>(W2, b2);
    }

    out_templates_kernel<<<8, 256>>>(out);
    out_attn_kernel<<<dim3(64, 8), 256>>>(out);
}